// round 1
// baseline (speedup 1.0000x reference)
#include <cuda_runtime.h>
#include <cuda_bf16.h>
#include <math.h>

// ---------------------------------------------------------------------------
// MultiheadSetAttention: fp32 baseline pipeline
//   1) Q = query @ Wq^T + b   -> head-split layout (b,h,nq,d)
//   2) K = key   @ Wk^T + b   -> (b,h,nk,d)
//   3) V = value @ Wv^T + b   -> (b,h,nk,d)
//   4) flash attention with log-multiplicity bias -> (b,nq,h*d)
//   5) out = A @ Wo^T + b     -> d_out (b,nq,e)
// ---------------------------------------------------------------------------

#define EMBED 1024
#define HEADS 16
#define HDIM  64
#define BATCH 4
#define NQ    1024
#define NK    2048

// Scratch (static device memory; allocation APIs are forbidden)
__device__ float g_Q[(size_t)BATCH * HEADS * NQ * HDIM];   // 4M floats
__device__ float g_K[(size_t)BATCH * HEADS * NK * HDIM];   // 8M
__device__ float g_V[(size_t)BATCH * HEADS * NK * HDIM];   // 8M
__device__ float g_A[(size_t)BATCH * NQ * EMBED];          // 4M

// ---------------------------------------------------------------------------
// GEMM: out = X @ W^T + bias.   X: (M, 1024) row-major, W: (1024, 1024) row-major.
// BM=BN=128, BK=16, 256 threads, 8x8 microtile per thread.
// split=1: write head-split layout given nPerBatch rows per batch.
// ---------------------------------------------------------------------------
#define BM 128
#define BN 128
#define BKK 16

__global__ __launch_bounds__(256, 2)
void gemm128(const float* __restrict__ A, const float* __restrict__ W,
             const float* __restrict__ bias, float* __restrict__ out,
             int M, int nPerBatch, int split)
{
    __shared__ float As[BKK][BM + 4];
    __shared__ float Bs[BKK][BN + 4];

    const int tid = threadIdx.x;
    const int tx = tid & 15;
    const int ty = tid >> 4;
    const int row0 = blockIdx.y * BM;
    const int col0 = blockIdx.x * BN;

    const int lr  = tid >> 2;   // 0..63, row within tile (two iters: +0, +64)
    const int lk4 = tid & 3;    // float4 index along k

    float acc[8][8];
#pragma unroll
    for (int i = 0; i < 8; i++)
#pragma unroll
        for (int j = 0; j < 8; j++) acc[i][j] = 0.f;

    for (int k0 = 0; k0 < EMBED; k0 += BKK) {
#pragma unroll
        for (int i = 0; i < 2; i++) {
            int r = lr + i * 64;
            float4 av = *(const float4*)&A[(size_t)(row0 + r) * EMBED + k0 + lk4 * 4];
            float4 bv = *(const float4*)&W[(size_t)(col0 + r) * EMBED + k0 + lk4 * 4];
            As[lk4 * 4 + 0][r] = av.x;
            As[lk4 * 4 + 1][r] = av.y;
            As[lk4 * 4 + 2][r] = av.z;
            As[lk4 * 4 + 3][r] = av.w;
            Bs[lk4 * 4 + 0][r] = bv.x;
            Bs[lk4 * 4 + 1][r] = bv.y;
            Bs[lk4 * 4 + 2][r] = bv.z;
            Bs[lk4 * 4 + 3][r] = bv.w;
        }
        __syncthreads();

#pragma unroll
        for (int kk = 0; kk < BKK; kk++) {
            float a[8], b[8];
            *(float4*)&a[0] = *(const float4*)&As[kk][ty * 8];
            *(float4*)&a[4] = *(const float4*)&As[kk][ty * 8 + 4];
            *(float4*)&b[0] = *(const float4*)&Bs[kk][tx * 8];
            *(float4*)&b[4] = *(const float4*)&Bs[kk][tx * 8 + 4];
#pragma unroll
            for (int i = 0; i < 8; i++)
#pragma unroll
                for (int j = 0; j < 8; j++)
                    acc[i][j] += a[i] * b[j];
        }
        __syncthreads();
    }

    // epilogue
#pragma unroll
    for (int i = 0; i < 8; i++) {
        int gr = row0 + ty * 8 + i;
        int bb = gr / nPerBatch;
        int n  = gr - bb * nPerBatch;
#pragma unroll
        for (int j = 0; j < 8; j++) {
            int c = col0 + tx * 8 + j;
            float v = acc[i][j] + bias[c];
            if (split) {
                int h = c >> 6;
                int d = c & 63;
                out[(((size_t)bb * HEADS + h) * nPerBatch + n) * HDIM + d] = v;
            } else {
                out[(size_t)gr * EMBED + c] = v;
            }
        }
    }
}

// ---------------------------------------------------------------------------
// Flash attention with multiplicity bias.
// Block: 128 threads handles 32 queries for one (b,h); loops over NK in
// 32-key chunks with online softmax. Thread t -> query q=t/4, lane-sub=t%4.
// Each thread accumulates 16 output dims (sub*16 .. +16).
// ---------------------------------------------------------------------------
#define AQ 32
#define AK 32

__global__ __launch_bounds__(128)
void attn_kernel(const float* __restrict__ Q, const float* __restrict__ K,
                 const float* __restrict__ V, const float* __restrict__ mult,
                 float* __restrict__ Out)
{
    __shared__ float Qs[AQ][68];
    __shared__ float Ks[AK][68];
    __shared__ float Vs[AK][68];
    __shared__ float Ps[AQ][36];
    __shared__ float Lm[AK];

    const int t  = threadIdx.x;
    const int bx = blockIdx.x;
    const int qt = bx & 31;           // NQ/AQ = 32 tiles
    const int h  = (bx >> 5) & 15;
    const int b  = bx >> 9;
    const int q0 = qt * AQ;

    const float* Qbase = Q + (((size_t)(b * HEADS + h) * NQ) + q0) * HDIM;
    const float* Kbase = K + ((size_t)(b * HEADS + h) * NK) * HDIM;
    const float* Vbase = V + ((size_t)(b * HEADS + h) * NK) * HDIM;
    const float* mbase = mult + (size_t)b * NK;

    // load Q tile (32x64) via float4: 512 float4, 128 threads -> 4 each
#pragma unroll
    for (int i = 0; i < 4; i++) {
        int f = t + i * 128;
        int r = f >> 4, c4 = f & 15;
        *(float4*)&Qs[r][c4 * 4] = *(const float4*)&Qbase[(size_t)r * HDIM + c4 * 4];
    }

    const int q   = t >> 2;
    const int sub = t & 3;

    float m = -INFINITY;
    float l = 0.f;
    float o[16];
#pragma unroll
    for (int d = 0; d < 16; d++) o[d] = 0.f;

    for (int c0 = 0; c0 < NK; c0 += AK) {
        __syncthreads();  // previous chunk's Ps/Vs reads complete
        // load K and V chunk (each 32x64) + log-multiplicities
#pragma unroll
        for (int i = 0; i < 4; i++) {
            int f = t + i * 128;
            int r = f >> 4, c4 = f & 15;
            *(float4*)&Ks[r][c4 * 4] = *(const float4*)&Kbase[((size_t)(c0 + r)) * HDIM + c4 * 4];
            *(float4*)&Vs[r][c4 * 4] = *(const float4*)&Vbase[((size_t)(c0 + r)) * HDIM + c4 * 4];
        }
        if (t < AK) Lm[t] = __logf(mbase[c0 + t]);
        __syncthreads();

        // scores: 8 keys per thread (keys sub*8 .. +8)
        float s[8];
#pragma unroll
        for (int j = 0; j < 8; j++) s[j] = 0.f;
#pragma unroll
        for (int d4 = 0; d4 < 16; d4++) {
            float4 qv = *(const float4*)&Qs[q][d4 * 4];
#pragma unroll
            for (int j = 0; j < 8; j++) {
                float4 kv = *(const float4*)&Ks[sub * 8 + j][d4 * 4];
                s[j] += qv.x * kv.x + qv.y * kv.y + qv.z * kv.z + qv.w * kv.w;
            }
        }
#pragma unroll
        for (int j = 0; j < 8; j++)
            s[j] = s[j] * 0.125f + Lm[sub * 8 + j];

        // online softmax update (4 lanes per row cooperate via shuffle)
        float cm = s[0];
#pragma unroll
        for (int j = 1; j < 8; j++) cm = fmaxf(cm, s[j]);
        cm = fmaxf(cm, __shfl_xor_sync(0xffffffffu, cm, 1));
        cm = fmaxf(cm, __shfl_xor_sync(0xffffffffu, cm, 2));
        float mnew  = fmaxf(m, cm);
        float alpha = __expf(m - mnew);
        float ssum = 0.f;
#pragma unroll
        for (int j = 0; j < 8; j++) {
            float p = __expf(s[j] - mnew);
            Ps[q][sub * 8 + j] = p;
            ssum += p;
        }
        ssum += __shfl_xor_sync(0xffffffffu, ssum, 1);
        ssum += __shfl_xor_sync(0xffffffffu, ssum, 2);
        l = l * alpha + ssum;
        m = mnew;
#pragma unroll
        for (int d = 0; d < 16; d++) o[d] *= alpha;
        __syncthreads();   // Ps visible to all 4 lanes of each row

        // O += P @ V  (this thread: all 32 keys x its 16 dims)
#pragma unroll
        for (int kk = 0; kk < AK; kk++) {
            float pv = Ps[q][kk];
            const float* vrow = &Vs[kk][sub * 16];
#pragma unroll
            for (int d4 = 0; d4 < 4; d4++) {
                float4 vv = *(const float4*)&vrow[d4 * 4];
                o[d4 * 4 + 0] += pv * vv.x;
                o[d4 * 4 + 1] += pv * vv.y;
                o[d4 * 4 + 2] += pv * vv.z;
                o[d4 * 4 + 3] += pv * vv.w;
            }
        }
    }

    const float inv = 1.f / l;
    // write to (b, nq, h*64 + sub*16 ..) layout
    float* op = Out + ((size_t)(b * NQ + q0 + q)) * EMBED + h * HDIM + sub * 16;
#pragma unroll
    for (int d4 = 0; d4 < 4; d4++) {
        float4 v;
        v.x = o[d4 * 4 + 0] * inv;
        v.y = o[d4 * 4 + 1] * inv;
        v.z = o[d4 * 4 + 2] * inv;
        v.w = o[d4 * 4 + 3] * inv;
        *(float4*)&op[d4 * 4] = v;
    }
}

// ---------------------------------------------------------------------------
// launch
// ---------------------------------------------------------------------------
extern "C" void kernel_launch(void* const* d_in, const int* in_sizes, int n_in,
                              void* d_out, int out_size)
{
    const float* query = (const float*)d_in[0];
    const float* key   = (const float*)d_in[1];
    const float* value = (const float*)d_in[2];
    const float* mult  = (const float*)d_in[3];
    const float* wq_w  = (const float*)d_in[4];
    const float* wq_b  = (const float*)d_in[5];
    const float* wk_w  = (const float*)d_in[6];
    const float* wk_b  = (const float*)d_in[7];
    const float* wv_w  = (const float*)d_in[8];
    const float* wv_b  = (const float*)d_in[9];
    const float* wo_w  = (const float*)d_in[10];
    const float* wo_b  = (const float*)d_in[11];
    float* out = (float*)d_out;

    float *gQ, *gK, *gV, *gA;
    cudaGetSymbolAddress((void**)&gQ, g_Q);
    cudaGetSymbolAddress((void**)&gK, g_K);
    cudaGetSymbolAddress((void**)&gV, g_V);
    cudaGetSymbolAddress((void**)&gA, g_A);

    const int MQ = BATCH * NQ;   // 4096
    const int MK = BATCH * NK;   // 8192

    dim3 blk(256);
    // Q/K/V projections -> head-split layouts
    gemm128<<<dim3(EMBED / BN, MQ / BM), blk>>>(query, wq_w, wq_b, gQ, MQ, NQ, 1);
    gemm128<<<dim3(EMBED / BN, MK / BM), blk>>>(key,   wk_w, wk_b, gK, MK, NK, 1);
    gemm128<<<dim3(EMBED / BN, MK / BM), blk>>>(value, wv_w, wv_b, gV, MK, NK, 1);

    // attention
    attn_kernel<<<BATCH * HEADS * (NQ / AQ), 128>>>(gQ, gK, gV, mult, gA);

    // output projection -> d_out
    gemm128<<<dim3(EMBED / BN, MQ / BM), blk>>>(gA, wo_w, wo_b, out, MQ, NQ, 0);
}

// round 7
// speedup vs baseline: 3.4199x; 3.4199x over previous
#include <cuda_runtime.h>
#include <cstdint>
#include <math.h>

#define EMBED 1024
#define HEADS 16
#define HDIM  64
#define BATCH 4
#define NQ    1024
#define NK    2048

// Scratch (static device memory)
__device__ float g_Q[(size_t)BATCH * HEADS * NQ * HDIM];   // (b,h,nq,d)
__device__ float g_K[(size_t)BATCH * HEADS * HDIM * NK];   // (b,h,d,nk)  TRANSPOSED
__device__ float g_V[(size_t)BATCH * HEADS * NK * HDIM];   // (b,h,nk,d)
__device__ float g_A[(size_t)BATCH * NQ * EMBED];          // (b,nq,e)

__device__ __forceinline__ uint32_t f2tf32(float f) {
    uint32_t r;
    asm("cvt.rna.tf32.f32 %0, %1;" : "=r"(r) : "f"(f));
    return r;
}

__device__ __forceinline__ void mma_tf32_16x8x8(float* c, const uint32_t* a, const uint32_t* b) {
    asm volatile(
        "mma.sync.aligned.m16n8k8.row.col.f32.tf32.tf32.f32 "
        "{%0,%1,%2,%3}, {%4,%5,%6,%7}, {%8,%9}, {%0,%1,%2,%3};"
        : "+f"(c[0]), "+f"(c[1]), "+f"(c[2]), "+f"(c[3])
        : "r"(a[0]), "r"(a[1]), "r"(a[2]), "r"(a[3]), "r"(b[0]), "r"(b[1]));
}

// ---------------------------------------------------------------------------
// GEMM via mma.sync tf32: out = X @ W^T + bias.
// CTA tile 128x128, BK=32, 256 threads = 8 warps (4 m x 2 n), warp tile 32x64.
// X: (M,1024) row-major; W: (1024,1024) row-major (rows = out cols).
// split: 0 plain (row,1024); 1 head-split (b,h,n,d); 2 transposed (b,h,d,n).
// Smem rows padded to 36 floats -> conflict-free fragment LDS.
// ---------------------------------------------------------------------------
#define PAD 36

__global__ __launch_bounds__(256, 2)
void gemm_mma(const float* __restrict__ A, const float* __restrict__ W,
              const float* __restrict__ bias, float* __restrict__ out,
              int nP, int split)
{
    __shared__ float As[128 * PAD];
    __shared__ float Bs[128 * PAD];

    const int tid = threadIdx.x;
    const int wid = tid >> 5;
    const int lane = tid & 31;
    const int g = lane >> 2;      // group 0..7
    const int t = lane & 3;       // thread-in-group 0..3
    const int wm = wid & 3;       // warp m index 0..3
    const int wn = wid >> 2;      // warp n index 0..1
    const int row0 = blockIdx.y * 128;
    const int col0 = blockIdx.x * 128;

    float c[2][8][4];
#pragma unroll
    for (int mt = 0; mt < 2; mt++)
#pragma unroll
        for (int nt = 0; nt < 8; nt++)
#pragma unroll
            for (int i = 0; i < 4; i++) c[mt][nt][i] = 0.f;

    const uint32_t* Asu = (const uint32_t*)As;
    const uint32_t* Bsu = (const uint32_t*)Bs;

    for (int k0 = 0; k0 < EMBED; k0 += 32) {
        // load chunk: 128 rows x 32 k, each thread 4 float4 per side
#pragma unroll
        for (int i = 0; i < 4; i++) {
            int f = tid + i * 256;
            int r = f >> 3, c4 = f & 7;
            float4 av = *(const float4*)(A + (size_t)(row0 + r) * EMBED + k0 + c4 * 4);
            float4 bv = *(const float4*)(W + (size_t)(col0 + r) * EMBED + k0 + c4 * 4);
            uint32_t* ap = (uint32_t*)&As[r * PAD + c4 * 4];
            uint32_t* bp = (uint32_t*)&Bs[r * PAD + c4 * 4];
            ap[0] = f2tf32(av.x); ap[1] = f2tf32(av.y); ap[2] = f2tf32(av.z); ap[3] = f2tf32(av.w);
            bp[0] = f2tf32(bv.x); bp[1] = f2tf32(bv.y); bp[2] = f2tf32(bv.z); bp[3] = f2tf32(bv.w);
        }
        __syncthreads();

#pragma unroll
        for (int ks = 0; ks < 4; ks++) {
            const int kk = ks * 8;
            uint32_t a[2][4];
#pragma unroll
            for (int mt = 0; mt < 2; mt++) {
                int rb = wm * 32 + mt * 16;
                a[mt][0] = Asu[(rb + g) * PAD + kk + t];
                a[mt][1] = Asu[(rb + g + 8) * PAD + kk + t];
                a[mt][2] = Asu[(rb + g) * PAD + kk + t + 4];
                a[mt][3] = Asu[(rb + g + 8) * PAD + kk + t + 4];
            }
#pragma unroll
            for (int nt = 0; nt < 8; nt++) {
                int nb = wn * 64 + nt * 8;
                uint32_t b[2];
                b[0] = Bsu[(nb + g) * PAD + kk + t];
                b[1] = Bsu[(nb + g) * PAD + kk + t + 4];
#pragma unroll
                for (int mt = 0; mt < 2; mt++)
                    mma_tf32_16x8x8(c[mt][nt], a[mt], b);
            }
        }
        __syncthreads();
    }

    // epilogue: thread (g,t) holds rows {g, g+8}, cols {2t, 2t+1} of each 16x8 tile
#pragma unroll
    for (int mt = 0; mt < 2; mt++) {
#pragma unroll
        for (int half = 0; half < 2; half++) {
            int grow = row0 + wm * 32 + mt * 16 + g + half * 8;
            int bb = grow / nP, n = grow - bb * nP;
#pragma unroll
            for (int nt = 0; nt < 8; nt++) {
                int gcol = col0 + wn * 64 + nt * 8 + t * 2;
                float v0 = c[mt][nt][half * 2 + 0] + bias[gcol];
                float v1 = c[mt][nt][half * 2 + 1] + bias[gcol + 1];
                if (split == 2) {
                    int h = gcol >> 6, d = gcol & 63;
                    size_t ob = (((size_t)bb * HEADS + h) * HDIM + d) * nP + n;
                    out[ob] = v0;
                    out[ob + nP] = v1;
                } else if (split == 1) {
                    int h = gcol >> 6, d = gcol & 63;
                    float2* op = (float2*)(out + (((size_t)bb * HEADS + h) * nP + n) * HDIM + d);
                    *op = make_float2(v0, v1);
                } else {
                    float2* op = (float2*)(out + (size_t)grow * EMBED + gcol);
                    *op = make_float2(v0, v1);
                }
            }
        }
    }
}

// ---------------------------------------------------------------------------
// Attention: 64 queries x 64-key chunks, 256 threads, 4x4 register microtiles.
// K is pre-transposed (b,h,d,n). Online softmax with log-multiplicity bias.
// ---------------------------------------------------------------------------
__global__ __launch_bounds__(256, 2)
void attn2(const float* __restrict__ Q, const float* __restrict__ Kt_g,
           const float* __restrict__ V, const float* __restrict__ mult,
           float* __restrict__ Out)
{
    extern __shared__ float sm[];
    float (*Qs)[68] = (float(*)[68])sm;                 // 64x68
    float (*Kt)[68] = (float(*)[68])(sm + 4352);        // 64(d) x 68(k)
    float (*Vs)[68] = (float(*)[68])(sm + 8704);        // 64(k) x 68(d)
    float (*Ps)[68] = (float(*)[68])(sm + 13056);       // 64(q) x 68(k)
    float* Lm = sm + 17408;                             // 64

    const int t  = threadIdx.x;
    const int bx = blockIdx.x;
    const int qt = bx & 15;
    const int h  = (bx >> 4) & 15;
    const int b  = bx >> 8;
    const int q0 = qt * 64;

    const float* Qbase = Q + (((size_t)(b * HEADS + h) * NQ) + q0) * HDIM;
    const float* Ktbase = Kt_g + ((size_t)(b * HEADS + h) * HDIM) * NK;
    const float* Vbase = V + ((size_t)(b * HEADS + h) * NK) * HDIM;
    const float* mbase = mult + (size_t)b * NK;

#pragma unroll
    for (int i = 0; i < 4; i++) {
        int f = t + i * 256;
        int r = f >> 4, c4 = f & 15;
        *(float4*)&Qs[r][c4 * 4] = *(const float4*)&Qbase[(size_t)r * HDIM + c4 * 4];
    }

    const int qg = t >> 4;   // 0..15: queries qg*4..+3
    const int kg = t & 15;   // score phase: keys kg*4..+3
    const int dg = t & 15;   // pv phase: dims dg*4..+3

    float m[4], l[4], o[4][4];
#pragma unroll
    for (int i = 0; i < 4; i++) {
        m[i] = -INFINITY; l[i] = 0.f;
#pragma unroll
        for (int j = 0; j < 4; j++) o[i][j] = 0.f;
    }

    for (int c0 = 0; c0 < NK; c0 += 64) {
        __syncthreads();
#pragma unroll
        for (int i = 0; i < 4; i++) {
            int f = t + i * 256;
            int r = f >> 4, c4 = f & 15;
            *(float4*)&Kt[r][c4 * 4] = *(const float4*)&Ktbase[(size_t)r * NK + c0 + c4 * 4];
            *(float4*)&Vs[r][c4 * 4] = *(const float4*)&Vbase[(size_t)(c0 + r) * HDIM + c4 * 4];
        }
        if (t < 64) Lm[t] = __logf(mbase[c0 + t]);
        __syncthreads();

        float s[4][4];
#pragma unroll
        for (int i = 0; i < 4; i++)
#pragma unroll
            for (int j = 0; j < 4; j++) s[i][j] = 0.f;

#pragma unroll
        for (int d4 = 0; d4 < 16; d4++) {
            float4 qv[4];
#pragma unroll
            for (int i = 0; i < 4; i++) qv[i] = *(const float4*)&Qs[qg * 4 + i][d4 * 4];
#pragma unroll
            for (int dd = 0; dd < 4; dd++) {
                float4 kt = *(const float4*)&Kt[d4 * 4 + dd][kg * 4];
#pragma unroll
                for (int i = 0; i < 4; i++) {
                    float qc = (dd == 0) ? qv[i].x : (dd == 1) ? qv[i].y : (dd == 2) ? qv[i].z : qv[i].w;
                    s[i][0] += qc * kt.x;
                    s[i][1] += qc * kt.y;
                    s[i][2] += qc * kt.z;
                    s[i][3] += qc * kt.w;
                }
            }
        }

        float alpha[4];
#pragma unroll
        for (int i = 0; i < 4; i++) {
            s[i][0] = s[i][0] * 0.125f + Lm[kg * 4 + 0];
            s[i][1] = s[i][1] * 0.125f + Lm[kg * 4 + 1];
            s[i][2] = s[i][2] * 0.125f + Lm[kg * 4 + 2];
            s[i][3] = s[i][3] * 0.125f + Lm[kg * 4 + 3];
            float rmax = fmaxf(fmaxf(s[i][0], s[i][1]), fmaxf(s[i][2], s[i][3]));
            rmax = fmaxf(rmax, __shfl_xor_sync(0xffffffffu, rmax, 1));
            rmax = fmaxf(rmax, __shfl_xor_sync(0xffffffffu, rmax, 2));
            rmax = fmaxf(rmax, __shfl_xor_sync(0xffffffffu, rmax, 4));
            rmax = fmaxf(rmax, __shfl_xor_sync(0xffffffffu, rmax, 8));
            float mnew = fmaxf(m[i], rmax);
            alpha[i] = __expf(m[i] - mnew);
            float4 p4;
            p4.x = __expf(s[i][0] - mnew);
            p4.y = __expf(s[i][1] - mnew);
            p4.z = __expf(s[i][2] - mnew);
            p4.w = __expf(s[i][3] - mnew);
            *(float4*)&Ps[qg * 4 + i][kg * 4] = p4;
            float rs = p4.x + p4.y + p4.z + p4.w;
            rs += __shfl_xor_sync(0xffffffffu, rs, 1);
            rs += __shfl_xor_sync(0xffffffffu, rs, 2);
            rs += __shfl_xor_sync(0xffffffffu, rs, 4);
            rs += __shfl_xor_sync(0xffffffffu, rs, 8);
            l[i] = l[i] * alpha[i] + rs;
            m[i] = mnew;
        }
        __syncthreads();

#pragma unroll
        for (int i = 0; i < 4; i++)
#pragma unroll
            for (int j = 0; j < 4; j++) o[i][j] *= alpha[i];

#pragma unroll
        for (int kk4 = 0; kk4 < 16; kk4++) {
            float4 pv[4];
#pragma unroll
            for (int i = 0; i < 4; i++) pv[i] = *(const float4*)&Ps[qg * 4 + i][kk4 * 4];
#pragma unroll
            for (int dd = 0; dd < 4; dd++) {
                float4 vv = *(const float4*)&Vs[kk4 * 4 + dd][dg * 4];
#pragma unroll
                for (int i = 0; i < 4; i++) {
                    float pc = (dd == 0) ? pv[i].x : (dd == 1) ? pv[i].y : (dd == 2) ? pv[i].z : pv[i].w;
                    o[i][0] += pc * vv.x;
                    o[i][1] += pc * vv.y;
                    o[i][2] += pc * vv.z;
                    o[i][3] += pc * vv.w;
                }
            }
        }
    }

#pragma unroll
    for (int i = 0; i < 4; i++) {
        float inv = 1.f / l[i];
        float4 v;
        v.x = o[i][0] * inv; v.y = o[i][1] * inv; v.z = o[i][2] * inv; v.w = o[i][3] * inv;
        *(float4*)&Out[((size_t)(b * NQ + q0 + qg * 4 + i)) * EMBED + h * HDIM + dg * 4] = v;
    }
}

// ---------------------------------------------------------------------------
// launch
// ---------------------------------------------------------------------------
extern "C" void kernel_launch(void* const* d_in, const int* in_sizes, int n_in,
                              void* d_out, int out_size)
{
    const float* query = (const float*)d_in[0];
    const float* key   = (const float*)d_in[1];
    const float* value = (const float*)d_in[2];
    const float* mult  = (const float*)d_in[3];
    const float* wq_w  = (const float*)d_in[4];
    const float* wq_b  = (const float*)d_in[5];
    const float* wk_w  = (const float*)d_in[6];
    const float* wk_b  = (const float*)d_in[7];
    const float* wv_w  = (const float*)d_in[8];
    const float* wv_b  = (const float*)d_in[9];
    const float* wo_w  = (const float*)d_in[10];
    const float* wo_b  = (const float*)d_in[11];
    float* out = (float*)d_out;

    float *gQ, *gK, *gV, *gA;
    cudaGetSymbolAddress((void**)&gQ, g_Q);
    cudaGetSymbolAddress((void**)&gK, g_K);
    cudaGetSymbolAddress((void**)&gV, g_V);
    cudaGetSymbolAddress((void**)&gA, g_A);

    const int ATTN_SMEM = 17472 * 4;
    cudaFuncSetAttribute(attn2, cudaFuncAttributeMaxDynamicSharedMemorySize, ATTN_SMEM);

    dim3 blk(256);
    // projections (mma.sync tf32)
    gemm_mma<<<dim3(8, 32), blk>>>(query, wq_w, wq_b, gQ, NQ, 1);
    gemm_mma<<<dim3(8, 64), blk>>>(key,   wk_w, wk_b, gK, NK, 2);
    gemm_mma<<<dim3(8, 64), blk>>>(value, wv_w, wv_b, gV, NK, 1);

    // attention
    attn2<<<BATCH * HEADS * (NQ / 64), blk, ATTN_SMEM>>>(gQ, gK, gV, mult, gA);

    // output projection
    gemm_mma<<<dim3(8, 32), blk>>>(gA, wo_w, wo_b, out, NQ, 0);
}

// round 8
// speedup vs baseline: 8.7944x; 2.5716x over previous
#include <cuda_runtime.h>
#include <cstdint>
#include <math.h>

#define EMBED 1024
#define HEADS 16
#define HDIM  64
#define BATCH 4
#define NQ    1024
#define NK    2048

// Scratch (static device memory)
__device__ float g_Q[(size_t)BATCH * HEADS * NQ * HDIM];   // (b,h,nq,d)
__device__ float g_K[(size_t)BATCH * HEADS * NK * HDIM];   // (b,h,nk,d)
__device__ float g_V[(size_t)BATCH * HEADS * NK * HDIM];   // (b,h,nk,d)
__device__ float g_A[(size_t)BATCH * NQ * EMBED];          // (b,nq,e)

__device__ __forceinline__ uint32_t f2tf32(float f) {
    uint32_t r;
    asm("cvt.rna.tf32.f32 %0, %1;" : "=r"(r) : "f"(f));
    return r;
}

__device__ __forceinline__ void mma_tf32_16x8x8(float* c, const uint32_t* a, const uint32_t* b) {
    asm volatile(
        "mma.sync.aligned.m16n8k8.row.col.f32.tf32.tf32.f32 "
        "{%0,%1,%2,%3}, {%4,%5,%6,%7}, {%8,%9}, {%0,%1,%2,%3};"
        : "+f"(c[0]), "+f"(c[1]), "+f"(c[2]), "+f"(c[3])
        : "r"(a[0]), "r"(a[1]), "r"(a[2]), "r"(a[3]), "r"(b[0]), "r"(b[1]));
}

// ---------------------------------------------------------------------------
// GEMM via mma.sync tf32: out = X @ W^T + bias.
// CTA tile 128x128, BK=32, 256 threads = 8 warps (4 m x 2 n), warp tile 32x64.
// split: 0 plain (row,1024); 1 head-split (b,h,n,d).
// ---------------------------------------------------------------------------
#define PAD 36

__global__ __launch_bounds__(256, 2)
void gemm_mma(const float* __restrict__ A, const float* __restrict__ W,
              const float* __restrict__ bias, float* __restrict__ out,
              int nP, int split)
{
    __shared__ float As[128 * PAD];
    __shared__ float Bs[128 * PAD];

    const int tid = threadIdx.x;
    const int wid = tid >> 5;
    const int lane = tid & 31;
    const int g = lane >> 2;
    const int t = lane & 3;
    const int wm = wid & 3;
    const int wn = wid >> 2;
    const int row0 = blockIdx.y * 128;
    const int col0 = blockIdx.x * 128;

    float c[2][8][4];
#pragma unroll
    for (int mt = 0; mt < 2; mt++)
#pragma unroll
        for (int nt = 0; nt < 8; nt++)
#pragma unroll
            for (int i = 0; i < 4; i++) c[mt][nt][i] = 0.f;

    const uint32_t* Asu = (const uint32_t*)As;
    const uint32_t* Bsu = (const uint32_t*)Bs;

    for (int k0 = 0; k0 < EMBED; k0 += 32) {
#pragma unroll
        for (int i = 0; i < 4; i++) {
            int f = tid + i * 256;
            int r = f >> 3, c4 = f & 7;
            float4 av = *(const float4*)(A + (size_t)(row0 + r) * EMBED + k0 + c4 * 4);
            float4 bv = *(const float4*)(W + (size_t)(col0 + r) * EMBED + k0 + c4 * 4);
            uint32_t* ap = (uint32_t*)&As[r * PAD + c4 * 4];
            uint32_t* bp = (uint32_t*)&Bs[r * PAD + c4 * 4];
            ap[0] = f2tf32(av.x); ap[1] = f2tf32(av.y); ap[2] = f2tf32(av.z); ap[3] = f2tf32(av.w);
            bp[0] = f2tf32(bv.x); bp[1] = f2tf32(bv.y); bp[2] = f2tf32(bv.z); bp[3] = f2tf32(bv.w);
        }
        __syncthreads();

#pragma unroll
        for (int ks = 0; ks < 4; ks++) {
            const int kk = ks * 8;
            uint32_t a[2][4];
#pragma unroll
            for (int mt = 0; mt < 2; mt++) {
                int rb = wm * 32 + mt * 16;
                a[mt][0] = Asu[(rb + g) * PAD + kk + t];
                a[mt][1] = Asu[(rb + g + 8) * PAD + kk + t];
                a[mt][2] = Asu[(rb + g) * PAD + kk + t + 4];
                a[mt][3] = Asu[(rb + g + 8) * PAD + kk + t + 4];
            }
#pragma unroll
            for (int nt = 0; nt < 8; nt++) {
                int nb = wn * 64 + nt * 8;
                uint32_t b[2];
                b[0] = Bsu[(nb + g) * PAD + kk + t];
                b[1] = Bsu[(nb + g) * PAD + kk + t + 4];
#pragma unroll
                for (int mt = 0; mt < 2; mt++)
                    mma_tf32_16x8x8(c[mt][nt], a[mt], b);
            }
        }
        __syncthreads();
    }

#pragma unroll
    for (int mt = 0; mt < 2; mt++) {
#pragma unroll
        for (int half = 0; half < 2; half++) {
            int grow = row0 + wm * 32 + mt * 16 + g + half * 8;
            int bb = grow / nP, n = grow - bb * nP;
#pragma unroll
            for (int nt = 0; nt < 8; nt++) {
                int gcol = col0 + wn * 64 + nt * 8 + t * 2;
                float v0 = c[mt][nt][half * 2 + 0] + bias[gcol];
                float v1 = c[mt][nt][half * 2 + 1] + bias[gcol + 1];
                if (split == 1) {
                    int h = gcol >> 6, d = gcol & 63;
                    float2* op = (float2*)(out + (((size_t)bb * HEADS + h) * nP + n) * HDIM + d);
                    *op = make_float2(v0, v1);
                } else {
                    float2* op = (float2*)(out + (size_t)grow * EMBED + gcol);
                    *op = make_float2(v0, v1);
                }
            }
        }
    }
}

// ---------------------------------------------------------------------------
// Attention via mma.sync tf32. CTA: 128 queries (8 warps x 16q), 64-key chunks.
// QK^T and P@V both on tensor cores; online softmax on accumulator fragments;
// P converted from C-fragment to A-fragment layout via warp shuffles.
// Smem row stride 68 words -> all fragment LDS conflict-free ((4t+g) mod 32).
// ---------------------------------------------------------------------------
#define ASTRIDE 68

__global__ __launch_bounds__(256, 2)
void attn3(const float* __restrict__ Q, const float* __restrict__ K,
           const float* __restrict__ V, const float* __restrict__ mult,
           float* __restrict__ Out)
{
    extern __shared__ uint32_t su[];
    uint32_t* Qs = su;                      // 128 x 68 tf32
    uint32_t* Ks = su + 128 * ASTRIDE;      // 64 x 68 tf32
    uint32_t* Vs = su + 192 * ASTRIDE;      // 64 x 68 tf32
    float*    Lm = (float*)(su + 256 * ASTRIDE);  // 64

    const int tid  = threadIdx.x;
    const int w    = tid >> 5;
    const int lane = tid & 31;
    const int g    = lane >> 2;
    const int tq   = lane & 3;
    const int bx = blockIdx.x;
    const int q0 = (bx & 7) * 128;
    const int h  = (bx >> 3) & 15;
    const int b  = bx >> 7;

    const float* Qbase = Q + (((size_t)(b * HEADS + h) * NQ) + q0) * HDIM;
    const float* Kbase = K + ((size_t)(b * HEADS + h) * NK) * HDIM;
    const float* Vbase = V + ((size_t)(b * HEADS + h) * NK) * HDIM;
    const float* mbase = mult + (size_t)b * NK;

    // load Q tile 128x64 -> tf32 smem (2048 float4 / 256 thr = 8 each)
#pragma unroll
    for (int i = 0; i < 8; i++) {
        int f = tid + i * 256;
        int r = f >> 4, c4 = f & 15;
        float4 qv = *(const float4*)(Qbase + (size_t)r * HDIM + c4 * 4);
        uint4 u = make_uint4(f2tf32(qv.x), f2tf32(qv.y), f2tf32(qv.z), f2tf32(qv.w));
        *(uint4*)&Qs[r * ASTRIDE + c4 * 4] = u;
    }

    const int qb = w * 16;                  // warp's q-row base within tile
    const int srcA = (lane & ~3) | (tq >> 1);
    const int srcB = srcA + 2;

    float m0 = -INFINITY, m1 = -INFINITY, l0 = 0.f, l1 = 0.f;
    float Oc[8][4];
#pragma unroll
    for (int dt = 0; dt < 8; dt++)
#pragma unroll
        for (int i = 0; i < 4; i++) Oc[dt][i] = 0.f;

    for (int c0 = 0; c0 < NK; c0 += 64) {
        __syncthreads();
        // K,V chunk 64x64 each (1024 float4 -> 4 per thread per tensor)
#pragma unroll
        for (int i = 0; i < 4; i++) {
            int f = tid + i * 256;
            int r = f >> 4, c4 = f & 15;
            float4 kv = *(const float4*)(Kbase + (size_t)(c0 + r) * HDIM + c4 * 4);
            float4 vv = *(const float4*)(Vbase + (size_t)(c0 + r) * HDIM + c4 * 4);
            *(uint4*)&Ks[r * ASTRIDE + c4 * 4] =
                make_uint4(f2tf32(kv.x), f2tf32(kv.y), f2tf32(kv.z), f2tf32(kv.w));
            *(uint4*)&Vs[r * ASTRIDE + c4 * 4] =
                make_uint4(f2tf32(vv.x), f2tf32(vv.y), f2tf32(vv.z), f2tf32(vv.w));
        }
        if (tid < 64) Lm[tid] = __logf(mbase[c0 + tid]);
        __syncthreads();

        // ---- S = Q K^T (warp: 16q x 64k) ----
        float Sc[8][4];
#pragma unroll
        for (int nt = 0; nt < 8; nt++)
#pragma unroll
            for (int i = 0; i < 4; i++) Sc[nt][i] = 0.f;

#pragma unroll
        for (int ks = 0; ks < 8; ks++) {
            const int kk = ks * 8;
            uint32_t a[4];
            a[0] = Qs[(qb + g) * ASTRIDE + kk + tq];
            a[1] = Qs[(qb + g + 8) * ASTRIDE + kk + tq];
            a[2] = Qs[(qb + g) * ASTRIDE + kk + tq + 4];
            a[3] = Qs[(qb + g + 8) * ASTRIDE + kk + tq + 4];
#pragma unroll
            for (int nt = 0; nt < 8; nt++) {
                const int nb = nt * 8;
                uint32_t bfr[2];
                bfr[0] = Ks[(nb + g) * ASTRIDE + kk + tq];
                bfr[1] = Ks[(nb + g) * ASTRIDE + kk + tq + 4];
                mma_tf32_16x8x8(Sc[nt], a, bfr);
            }
        }

        // ---- online softmax on fragments ----
        float rmax0 = -INFINITY, rmax1 = -INFINITY;
#pragma unroll
        for (int nt = 0; nt < 8; nt++) {
            float lmA = Lm[nt * 8 + 2 * tq];
            float lmB = Lm[nt * 8 + 2 * tq + 1];
            Sc[nt][0] = Sc[nt][0] * 0.125f + lmA;
            Sc[nt][1] = Sc[nt][1] * 0.125f + lmB;
            Sc[nt][2] = Sc[nt][2] * 0.125f + lmA;
            Sc[nt][3] = Sc[nt][3] * 0.125f + lmB;
            rmax0 = fmaxf(rmax0, fmaxf(Sc[nt][0], Sc[nt][1]));
            rmax1 = fmaxf(rmax1, fmaxf(Sc[nt][2], Sc[nt][3]));
        }
        rmax0 = fmaxf(rmax0, __shfl_xor_sync(0xffffffffu, rmax0, 1));
        rmax0 = fmaxf(rmax0, __shfl_xor_sync(0xffffffffu, rmax0, 2));
        rmax1 = fmaxf(rmax1, __shfl_xor_sync(0xffffffffu, rmax1, 1));
        rmax1 = fmaxf(rmax1, __shfl_xor_sync(0xffffffffu, rmax1, 2));

        float mn0 = fmaxf(m0, rmax0);
        float mn1 = fmaxf(m1, rmax1);
        float alpha0 = __expf(m0 - mn0);
        float alpha1 = __expf(m1 - mn1);
        m0 = mn0; m1 = mn1;

        float ls0 = 0.f, ls1 = 0.f;
#pragma unroll
        for (int nt = 0; nt < 8; nt++) {
            Sc[nt][0] = __expf(Sc[nt][0] - mn0);
            Sc[nt][1] = __expf(Sc[nt][1] - mn0);
            Sc[nt][2] = __expf(Sc[nt][2] - mn1);
            Sc[nt][3] = __expf(Sc[nt][3] - mn1);
            ls0 += Sc[nt][0] + Sc[nt][1];
            ls1 += Sc[nt][2] + Sc[nt][3];
        }
        ls0 += __shfl_xor_sync(0xffffffffu, ls0, 1);
        ls0 += __shfl_xor_sync(0xffffffffu, ls0, 2);
        ls1 += __shfl_xor_sync(0xffffffffu, ls1, 1);
        ls1 += __shfl_xor_sync(0xffffffffu, ls1, 2);
        l0 = l0 * alpha0 + ls0;
        l1 = l1 * alpha1 + ls1;

        // rescale O
#pragma unroll
        for (int dt = 0; dt < 8; dt++) {
            Oc[dt][0] *= alpha0; Oc[dt][1] *= alpha0;
            Oc[dt][2] *= alpha1; Oc[dt][3] *= alpha1;
        }

        // ---- convert P (C-frag) -> A-frag layout, in place as tf32 bits ----
#pragma unroll
        for (int nt = 0; nt < 8; nt++) {
            float y0 = __shfl_sync(0xffffffffu, Sc[nt][0], srcA);
            float y1 = __shfl_sync(0xffffffffu, Sc[nt][1], srcA);
            float y2 = __shfl_sync(0xffffffffu, Sc[nt][0], srcB);
            float y3 = __shfl_sync(0xffffffffu, Sc[nt][1], srcB);
            float z0 = __shfl_sync(0xffffffffu, Sc[nt][2], srcA);
            float z1 = __shfl_sync(0xffffffffu, Sc[nt][3], srcA);
            float z2 = __shfl_sync(0xffffffffu, Sc[nt][2], srcB);
            float z3 = __shfl_sync(0xffffffffu, Sc[nt][3], srcB);
            uint32_t a0 = f2tf32((tq & 1) ? y1 : y0);
            uint32_t a1 = f2tf32((tq & 1) ? z1 : z0);
            uint32_t a2 = f2tf32((tq & 1) ? y3 : y2);
            uint32_t a3 = f2tf32((tq & 1) ? z3 : z2);
            Sc[nt][0] = __uint_as_float(a0);
            Sc[nt][1] = __uint_as_float(a1);
            Sc[nt][2] = __uint_as_float(a2);
            Sc[nt][3] = __uint_as_float(a3);
        }

        // ---- O += P V (key-steps = 8, dim-tiles = 8) ----
#pragma unroll
        for (int ks = 0; ks < 8; ks++) {
            const int kk = ks * 8;
            uint32_t a[4];
            a[0] = __float_as_uint(Sc[ks][0]);
            a[1] = __float_as_uint(Sc[ks][1]);
            a[2] = __float_as_uint(Sc[ks][2]);
            a[3] = __float_as_uint(Sc[ks][3]);
#pragma unroll
            for (int dt = 0; dt < 8; dt++) {
                const int nb = dt * 8;
                uint32_t bfr[2];
                bfr[0] = Vs[(kk + tq) * ASTRIDE + nb + g];
                bfr[1] = Vs[(kk + tq + 4) * ASTRIDE + nb + g];
                mma_tf32_16x8x8(Oc[dt], a, bfr);
            }
        }
    }

    // ---- write out: (b, q, h*64 + d) ----
    const float inv0 = 1.f / l0;
    const float inv1 = 1.f / l1;
    const int qg0 = q0 + qb + g;
    float* o0 = Out + ((size_t)(b * NQ + qg0)) * EMBED + h * HDIM;
    float* o1 = o0 + (size_t)8 * EMBED;
#pragma unroll
    for (int dt = 0; dt < 8; dt++) {
        int col = dt * 8 + 2 * tq;
        *(float2*)(o0 + col) = make_float2(Oc[dt][0] * inv0, Oc[dt][1] * inv0);
        *(float2*)(o1 + col) = make_float2(Oc[dt][2] * inv1, Oc[dt][3] * inv1);
    }
}

// ---------------------------------------------------------------------------
// launch
// ---------------------------------------------------------------------------
extern "C" void kernel_launch(void* const* d_in, const int* in_sizes, int n_in,
                              void* d_out, int out_size)
{
    const float* query = (const float*)d_in[0];
    const float* key   = (const float*)d_in[1];
    const float* value = (const float*)d_in[2];
    const float* mult  = (const float*)d_in[3];
    const float* wq_w  = (const float*)d_in[4];
    const float* wq_b  = (const float*)d_in[5];
    const float* wk_w  = (const float*)d_in[6];
    const float* wk_b  = (const float*)d_in[7];
    const float* wv_w  = (const float*)d_in[8];
    const float* wv_b  = (const float*)d_in[9];
    const float* wo_w  = (const float*)d_in[10];
    const float* wo_b  = (const float*)d_in[11];
    float* out = (float*)d_out;

    float *gQ, *gK, *gV, *gA;
    cudaGetSymbolAddress((void**)&gQ, g_Q);
    cudaGetSymbolAddress((void**)&gK, g_K);
    cudaGetSymbolAddress((void**)&gV, g_V);
    cudaGetSymbolAddress((void**)&gA, g_A);

    const int ATTN_SMEM = (256 * ASTRIDE + 64) * 4;   // ~69.9 KB
    cudaFuncSetAttribute(attn3, cudaFuncAttributeMaxDynamicSharedMemorySize, ATTN_SMEM);

    dim3 blk(256);
    // projections (mma.sync tf32)
    gemm_mma<<<dim3(8, 32), blk>>>(query, wq_w, wq_b, gQ, NQ, 1);
    gemm_mma<<<dim3(8, 64), blk>>>(key,   wk_w, wk_b, gK, NK, 1);
    gemm_mma<<<dim3(8, 64), blk>>>(value, wv_w, wv_b, gV, NK, 1);

    // attention (mma.sync tf32)
    attn3<<<BATCH * HEADS * (NQ / 128), blk, ATTN_SMEM>>>(gQ, gK, gV, mult, gA);

    // output projection
    gemm_mma<<<dim3(8, 32), blk>>>(gA, wo_w, wo_b, out, NQ, 0);
}

// round 9
// speedup vs baseline: 9.2526x; 1.0521x over previous
#include <cuda_runtime.h>
#include <cstdint>
#include <math.h>

#define EMBED 1024
#define HEADS 16
#define HDIM  64
#define BATCH 4
#define NQ    1024
#define NK    2048

// Scratch (static device memory)
__device__ float g_Q[(size_t)BATCH * HEADS * NQ * HDIM];   // (b,h,nq,d) tf32-rounded
__device__ float g_K[(size_t)BATCH * HEADS * NK * HDIM];   // (b,h,nk,d) tf32-rounded
__device__ float g_V[(size_t)BATCH * HEADS * NK * HDIM];   // (b,h,nk,d) tf32-rounded
__device__ float g_A[(size_t)BATCH * NQ * EMBED];          // (b,nq,e)   tf32-rounded
// tf32-rounded copies of inputs / weights
__device__ float g_Xq[(size_t)BATCH * NQ * EMBED];
__device__ float g_Xk[(size_t)BATCH * NK * EMBED];
__device__ float g_Xv[(size_t)BATCH * NK * EMBED];
__device__ float g_Wq[(size_t)EMBED * EMBED];
__device__ float g_Wk[(size_t)EMBED * EMBED];
__device__ float g_Wv[(size_t)EMBED * EMBED];
__device__ float g_Wo[(size_t)EMBED * EMBED];

__device__ __forceinline__ uint32_t f2tf32(float f) {
    uint32_t r;
    asm("cvt.rna.tf32.f32 %0, %1;" : "=r"(r) : "f"(f));
    return r;
}
__device__ __forceinline__ uint32_t smem_u32(const void* p) {
    return (uint32_t)__cvta_generic_to_shared(p);
}

#define CP_ASYNC16(dst_u32, src_ptr) \
    asm volatile("cp.async.cg.shared.global [%0], [%1], 16;" :: "r"(dst_u32), "l"(src_ptr))
#define CP_COMMIT() asm volatile("cp.async.commit_group;")
#define CP_WAIT1()  asm volatile("cp.async.wait_group 1;")

__device__ __forceinline__ void mma_tf32_16x8x8(float* c, const uint32_t* a, const uint32_t* b) {
    asm volatile(
        "mma.sync.aligned.m16n8k8.row.col.f32.tf32.tf32.f32 "
        "{%0,%1,%2,%3}, {%4,%5,%6,%7}, {%8,%9}, {%0,%1,%2,%3};"
        : "+f"(c[0]), "+f"(c[1]), "+f"(c[2]), "+f"(c[3])
        : "r"(a[0]), "r"(a[1]), "r"(a[2]), "r"(a[3]), "r"(b[0]), "r"(b[1]));
}

// ---------------------------------------------------------------------------
// Prepass: round fp32 -> tf32-representable fp32 (rna)
// ---------------------------------------------------------------------------
__global__ __launch_bounds__(256)
void cvt_tf32(const float4* __restrict__ src, float4* __restrict__ dst, int n4)
{
    int i = blockIdx.x * 256 + threadIdx.x;
    if (i < n4) {
        float4 v = src[i];
        float4 o;
        o.x = __uint_as_float(f2tf32(v.x));
        o.y = __uint_as_float(f2tf32(v.y));
        o.z = __uint_as_float(f2tf32(v.z));
        o.w = __uint_as_float(f2tf32(v.w));
        dst[i] = o;
    }
}

// ---------------------------------------------------------------------------
// GEMM via mma.sync tf32 + cp.async double buffering.
// out = X @ W^T + bias. CTA tile 128x128, BK=32, 8 warps (4m x 2n).
// Operands MUST be pre-rounded to tf32. split: 0 plain; 1 head-split (round out).
// ---------------------------------------------------------------------------
#define PAD 36
#define STG_W (128 * PAD)          // words per tensor per stage (4608)

__global__ __launch_bounds__(256, 2)
void gemm_mma2(const float* __restrict__ A, const float* __restrict__ W,
               const float* __restrict__ bias, float* __restrict__ out,
               int nP, int split)
{
    extern __shared__ float smf[];   // 2 stages x (A,B) x 4608 words = 73728 B

    const int tid = threadIdx.x;
    const int wid = tid >> 5;
    const int lane = tid & 31;
    const int g = lane >> 2;
    const int t = lane & 3;
    const int wm = wid & 3;
    const int wn = wid >> 2;
    const int row0 = blockIdx.y * 128;
    const int col0 = blockIdx.x * 128;

    const int lr = tid >> 3;        // 0..31? no: 256/8 -> r = f>>3 below
    (void)lr;

    float c[2][8][4];
#pragma unroll
    for (int mt = 0; mt < 2; mt++)
#pragma unroll
        for (int nt = 0; nt < 8; nt++)
#pragma unroll
            for (int i = 0; i < 4; i++) c[mt][nt][i] = 0.f;

    // prefetch helper (4 x 16B per tensor per thread)
    auto load_stage = [&](int s, int k0) {
        float* As = smf + s * (2 * STG_W);
        float* Bs = As + STG_W;
#pragma unroll
        for (int i = 0; i < 4; i++) {
            int f = tid + i * 256;
            int r = f >> 3, c4 = f & 7;
            CP_ASYNC16(smem_u32(&As[r * PAD + c4 * 4]),
                       A + (size_t)(row0 + r) * EMBED + k0 + c4 * 4);
            CP_ASYNC16(smem_u32(&Bs[r * PAD + c4 * 4]),
                       W + (size_t)(col0 + r) * EMBED + k0 + c4 * 4);
        }
    };

    load_stage(0, 0);  CP_COMMIT();
    load_stage(1, 32); CP_COMMIT();

    for (int it = 0; it < 32; it++) {
        CP_WAIT1();
        __syncthreads();
        const float* As = smf + (it & 1) * (2 * STG_W);
        const float* Bs = As + STG_W;
        const uint32_t* Asu = (const uint32_t*)As;
        const uint32_t* Bsu = (const uint32_t*)Bs;

#pragma unroll
        for (int ks = 0; ks < 4; ks++) {
            const int kk = ks * 8;
            uint32_t a[2][4];
#pragma unroll
            for (int mt = 0; mt < 2; mt++) {
                int rb = wm * 32 + mt * 16;
                a[mt][0] = Asu[(rb + g) * PAD + kk + t];
                a[mt][1] = Asu[(rb + g + 8) * PAD + kk + t];
                a[mt][2] = Asu[(rb + g) * PAD + kk + t + 4];
                a[mt][3] = Asu[(rb + g + 8) * PAD + kk + t + 4];
            }
#pragma unroll
            for (int nt = 0; nt < 8; nt++) {
                int nb = wn * 64 + nt * 8;
                uint32_t b[2];
                b[0] = Bsu[(nb + g) * PAD + kk + t];
                b[1] = Bsu[(nb + g) * PAD + kk + t + 4];
#pragma unroll
                for (int mt = 0; mt < 2; mt++)
                    mma_tf32_16x8x8(c[mt][nt], a[mt], b);
            }
        }
        __syncthreads();
        if (it + 2 < 32) load_stage(it & 1, (it + 2) * 32);
        CP_COMMIT();
    }

    // epilogue
#pragma unroll
    for (int mt = 0; mt < 2; mt++) {
#pragma unroll
        for (int half = 0; half < 2; half++) {
            int grow = row0 + wm * 32 + mt * 16 + g + half * 8;
            int bb = grow / nP, n = grow - bb * nP;
#pragma unroll
            for (int nt = 0; nt < 8; nt++) {
                int gcol = col0 + wn * 64 + nt * 8 + t * 2;
                float v0 = c[mt][nt][half * 2 + 0] + bias[gcol];
                float v1 = c[mt][nt][half * 2 + 1] + bias[gcol + 1];
                if (split == 1) {
                    v0 = __uint_as_float(f2tf32(v0));
                    v1 = __uint_as_float(f2tf32(v1));
                    int h = gcol >> 6, d = gcol & 63;
                    float2* op = (float2*)(out + (((size_t)bb * HEADS + h) * nP + n) * HDIM + d);
                    *op = make_float2(v0, v1);
                } else {
                    float2* op = (float2*)(out + (size_t)grow * EMBED + gcol);
                    *op = make_float2(v0, v1);
                }
            }
        }
    }
}

// ---------------------------------------------------------------------------
// Attention via mma.sync tf32 + cp.async double-buffered K/V chunks.
// CTA: 128 queries (8 warps x 16q), 64-key chunks. Operands pre-rounded tf32.
// log-multiplicities: per-lane float2 LDG + __logf + shuffles (no smem).
// ---------------------------------------------------------------------------
#define ASTRIDE 68
#define KV_W (64 * ASTRIDE)        // words per tensor per stage (4352)

__global__ __launch_bounds__(256, 2)
void attn4(const float* __restrict__ Q, const float* __restrict__ K,
           const float* __restrict__ V, const float* __restrict__ mult,
           float* __restrict__ Out)
{
    extern __shared__ uint32_t su[];
    uint32_t* Qs = su;                                  // 128 x 68
    // stage s: Ks = su + 8704 + s*8704 ; Vs = +4352

    const int tid  = threadIdx.x;
    const int w    = tid >> 5;
    const int lane = tid & 31;
    const int g    = lane >> 2;
    const int tq   = lane & 3;
    const int bx = blockIdx.x;
    const int q0 = (bx & 7) * 128;
    const int h  = (bx >> 3) & 15;
    const int b  = bx >> 7;

    const float* Qbase = Q + (((size_t)(b * HEADS + h) * NQ) + q0) * HDIM;
    const float* Kbase = K + ((size_t)(b * HEADS + h) * NK) * HDIM;
    const float* Vbase = V + ((size_t)(b * HEADS + h) * NK) * HDIM;
    const float* mbase = mult + (size_t)b * NK;

    // Q tile 128x64 via cp.async (8 x 16B per thread)
#pragma unroll
    for (int i = 0; i < 8; i++) {
        int f = tid + i * 256;
        int r = f >> 4, c4 = f & 15;
        CP_ASYNC16(smem_u32(&Qs[r * ASTRIDE + c4 * 4]),
                   Qbase + (size_t)r * HDIM + c4 * 4);
    }
    CP_COMMIT();

    auto load_kv = [&](int s, int c0) {
        uint32_t* Ks = su + 8704 + s * (2 * KV_W);
        uint32_t* Vs = Ks + KV_W;
#pragma unroll
        for (int i = 0; i < 4; i++) {
            int f = tid + i * 256;
            int r = f >> 4, c4 = f & 15;
            CP_ASYNC16(smem_u32(&Ks[r * ASTRIDE + c4 * 4]),
                       Kbase + (size_t)(c0 + r) * HDIM + c4 * 4);
            CP_ASYNC16(smem_u32(&Vs[r * ASTRIDE + c4 * 4]),
                       Vbase + (size_t)(c0 + r) * HDIM + c4 * 4);
        }
    };

    load_kv(0, 0);  CP_COMMIT();
    load_kv(1, 64); CP_COMMIT();

    const int qb = w * 16;
    const int srcA = (lane & ~3) | (tq >> 1);
    const int srcB = srcA + 2;
    const int lmsrc_base = tq;       // lane for Lm shuffle: nt*4 + tq

    float m0 = -INFINITY, m1 = -INFINITY, l0 = 0.f, l1 = 0.f;
    float Oc[8][4];
#pragma unroll
    for (int dt = 0; dt < 8; dt++)
#pragma unroll
        for (int i = 0; i < 4; i++) Oc[dt][i] = 0.f;

    for (int c0 = 0; c0 < NK; c0 += 64) {
        const int stg = (c0 >> 6) & 1;
        // multiplicities for this chunk: lane holds keys 2*lane, 2*lane+1
        float2 mv = *(const float2*)(mbase + c0 + 2 * lane);
        float lm0 = __logf(mv.x);
        float lm1 = __logf(mv.y);

        CP_WAIT1();
        __syncthreads();
        const uint32_t* Ks = su + 8704 + stg * (2 * KV_W);
        const uint32_t* Vs = Ks + KV_W;

        // ---- S = Q K^T ----
        float Sc[8][4];
#pragma unroll
        for (int nt = 0; nt < 8; nt++)
#pragma unroll
            for (int i = 0; i < 4; i++) Sc[nt][i] = 0.f;

#pragma unroll
        for (int ks = 0; ks < 8; ks++) {
            const int kk = ks * 8;
            uint32_t a[4];
            a[0] = Qs[(qb + g) * ASTRIDE + kk + tq];
            a[1] = Qs[(qb + g + 8) * ASTRIDE + kk + tq];
            a[2] = Qs[(qb + g) * ASTRIDE + kk + tq + 4];
            a[3] = Qs[(qb + g + 8) * ASTRIDE + kk + tq + 4];
#pragma unroll
            for (int nt = 0; nt < 8; nt++) {
                const int nb = nt * 8;
                uint32_t bfr[2];
                bfr[0] = Ks[(nb + g) * ASTRIDE + kk + tq];
                bfr[1] = Ks[(nb + g) * ASTRIDE + kk + tq + 4];
                mma_tf32_16x8x8(Sc[nt], a, bfr);
            }
        }

        // ---- softmax ----
        float rmax0 = -INFINITY, rmax1 = -INFINITY;
#pragma unroll
        for (int nt = 0; nt < 8; nt++) {
            float lmA = __shfl_sync(0xffffffffu, lm0, nt * 4 + lmsrc_base);
            float lmB = __shfl_sync(0xffffffffu, lm1, nt * 4 + lmsrc_base);
            Sc[nt][0] = Sc[nt][0] * 0.125f + lmA;
            Sc[nt][1] = Sc[nt][1] * 0.125f + lmB;
            Sc[nt][2] = Sc[nt][2] * 0.125f + lmA;
            Sc[nt][3] = Sc[nt][3] * 0.125f + lmB;
            rmax0 = fmaxf(rmax0, fmaxf(Sc[nt][0], Sc[nt][1]));
            rmax1 = fmaxf(rmax1, fmaxf(Sc[nt][2], Sc[nt][3]));
        }
        rmax0 = fmaxf(rmax0, __shfl_xor_sync(0xffffffffu, rmax0, 1));
        rmax0 = fmaxf(rmax0, __shfl_xor_sync(0xffffffffu, rmax0, 2));
        rmax1 = fmaxf(rmax1, __shfl_xor_sync(0xffffffffu, rmax1, 1));
        rmax1 = fmaxf(rmax1, __shfl_xor_sync(0xffffffffu, rmax1, 2));

        float mn0 = fmaxf(m0, rmax0);
        float mn1 = fmaxf(m1, rmax1);
        float alpha0 = __expf(m0 - mn0);
        float alpha1 = __expf(m1 - mn1);
        m0 = mn0; m1 = mn1;

        float ls0 = 0.f, ls1 = 0.f;
#pragma unroll
        for (int nt = 0; nt < 8; nt++) {
            Sc[nt][0] = __expf(Sc[nt][0] - mn0);
            Sc[nt][1] = __expf(Sc[nt][1] - mn0);
            Sc[nt][2] = __expf(Sc[nt][2] - mn1);
            Sc[nt][3] = __expf(Sc[nt][3] - mn1);
            ls0 += Sc[nt][0] + Sc[nt][1];
            ls1 += Sc[nt][2] + Sc[nt][3];
        }
        ls0 += __shfl_xor_sync(0xffffffffu, ls0, 1);
        ls0 += __shfl_xor_sync(0xffffffffu, ls0, 2);
        ls1 += __shfl_xor_sync(0xffffffffu, ls1, 1);
        ls1 += __shfl_xor_sync(0xffffffffu, ls1, 2);
        l0 = l0 * alpha0 + ls0;
        l1 = l1 * alpha1 + ls1;

#pragma unroll
        for (int dt = 0; dt < 8; dt++) {
            Oc[dt][0] *= alpha0; Oc[dt][1] *= alpha0;
            Oc[dt][2] *= alpha1; Oc[dt][3] *= alpha1;
        }

        // ---- P: C-frag -> A-frag ----
#pragma unroll
        for (int nt = 0; nt < 8; nt++) {
            float y0 = __shfl_sync(0xffffffffu, Sc[nt][0], srcA);
            float y1 = __shfl_sync(0xffffffffu, Sc[nt][1], srcA);
            float y2 = __shfl_sync(0xffffffffu, Sc[nt][0], srcB);
            float y3 = __shfl_sync(0xffffffffu, Sc[nt][1], srcB);
            float z0 = __shfl_sync(0xffffffffu, Sc[nt][2], srcA);
            float z1 = __shfl_sync(0xffffffffu, Sc[nt][3], srcA);
            float z2 = __shfl_sync(0xffffffffu, Sc[nt][2], srcB);
            float z3 = __shfl_sync(0xffffffffu, Sc[nt][3], srcB);
            Sc[nt][0] = __uint_as_float(f2tf32((tq & 1) ? y1 : y0));
            Sc[nt][1] = __uint_as_float(f2tf32((tq & 1) ? z1 : z0));
            Sc[nt][2] = __uint_as_float(f2tf32((tq & 1) ? y3 : y2));
            Sc[nt][3] = __uint_as_float(f2tf32((tq & 1) ? z3 : z2));
        }

        // ---- O += P V ----
#pragma unroll
        for (int ks = 0; ks < 8; ks++) {
            const int kk = ks * 8;
            uint32_t a[4];
            a[0] = __float_as_uint(Sc[ks][0]);
            a[1] = __float_as_uint(Sc[ks][1]);
            a[2] = __float_as_uint(Sc[ks][2]);
            a[3] = __float_as_uint(Sc[ks][3]);
#pragma unroll
            for (int dt = 0; dt < 8; dt++) {
                const int nb = dt * 8;
                uint32_t bfr[2];
                bfr[0] = Vs[(kk + tq) * ASTRIDE + nb + g];
                bfr[1] = Vs[(kk + tq + 4) * ASTRIDE + nb + g];
                mma_tf32_16x8x8(Oc[dt], a, bfr);
            }
        }

        __syncthreads();
        if (c0 + 128 < NK) load_kv(stg, c0 + 128);
        CP_COMMIT();
    }

    // ---- write out (tf32-rounded; consumed by final gemm) ----
    const float inv0 = 1.f / l0;
    const float inv1 = 1.f / l1;
    const int qg0 = q0 + qb + g;
    float* o0 = Out + ((size_t)(b * NQ + qg0)) * EMBED + h * HDIM;
    float* o1 = o0 + (size_t)8 * EMBED;
#pragma unroll
    for (int dt = 0; dt < 8; dt++) {
        int col = dt * 8 + 2 * tq;
        *(float2*)(o0 + col) = make_float2(__uint_as_float(f2tf32(Oc[dt][0] * inv0)),
                                           __uint_as_float(f2tf32(Oc[dt][1] * inv0)));
        *(float2*)(o1 + col) = make_float2(__uint_as_float(f2tf32(Oc[dt][2] * inv1)),
                                           __uint_as_float(f2tf32(Oc[dt][3] * inv1)));
    }
}

// ---------------------------------------------------------------------------
// launch
// ---------------------------------------------------------------------------
extern "C" void kernel_launch(void* const* d_in, const int* in_sizes, int n_in,
                              void* d_out, int out_size)
{
    const float* query = (const float*)d_in[0];
    const float* key   = (const float*)d_in[1];
    const float* value = (const float*)d_in[2];
    const float* mult  = (const float*)d_in[3];
    const float* wq_w  = (const float*)d_in[4];
    const float* wq_b  = (const float*)d_in[5];
    const float* wk_w  = (const float*)d_in[6];
    const float* wk_b  = (const float*)d_in[7];
    const float* wv_w  = (const float*)d_in[8];
    const float* wv_b  = (const float*)d_in[9];
    const float* wo_w  = (const float*)d_in[10];
    const float* wo_b  = (const float*)d_in[11];
    float* out = (float*)d_out;

    float *gQ, *gK, *gV, *gA, *gXq, *gXk, *gXv, *gWq, *gWk, *gWv, *gWo;
    cudaGetSymbolAddress((void**)&gQ, g_Q);
    cudaGetSymbolAddress((void**)&gK, g_K);
    cudaGetSymbolAddress((void**)&gV, g_V);
    cudaGetSymbolAddress((void**)&gA, g_A);
    cudaGetSymbolAddress((void**)&gXq, g_Xq);
    cudaGetSymbolAddress((void**)&gXk, g_Xk);
    cudaGetSymbolAddress((void**)&gXv, g_Xv);
    cudaGetSymbolAddress((void**)&gWq, g_Wq);
    cudaGetSymbolAddress((void**)&gWk, g_Wk);
    cudaGetSymbolAddress((void**)&gWv, g_Wv);
    cudaGetSymbolAddress((void**)&gWo, g_Wo);

    const int GEMM_SMEM = 2 * 2 * STG_W * 4;                 // 73728
    const int ATTN_SMEM = (128 * ASTRIDE + 2 * 2 * KV_W) * 4; // 104448
    cudaFuncSetAttribute(gemm_mma2, cudaFuncAttributeMaxDynamicSharedMemorySize, GEMM_SMEM);
    cudaFuncSetAttribute(attn4, cudaFuncAttributeMaxDynamicSharedMemorySize, ATTN_SMEM);

    dim3 blk(256);
    // tf32 prepass (rounding)
    const int NQ4 = BATCH * NQ * EMBED / 4;   // 1,048,576
    const int NK4 = BATCH * NK * EMBED / 4;   // 2,097,152
    const int NW4 = EMBED * EMBED / 4;        // 262,144
    cvt_tf32<<<NQ4 / 256, blk>>>((const float4*)query, (float4*)gXq, NQ4);
    cvt_tf32<<<NK4 / 256, blk>>>((const float4*)key,   (float4*)gXk, NK4);
    cvt_tf32<<<NK4 / 256, blk>>>((const float4*)value, (float4*)gXv, NK4);
    cvt_tf32<<<NW4 / 256, blk>>>((const float4*)wq_w, (float4*)gWq, NW4);
    cvt_tf32<<<NW4 / 256, blk>>>((const float4*)wk_w, (float4*)gWk, NW4);
    cvt_tf32<<<NW4 / 256, blk>>>((const float4*)wv_w, (float4*)gWv, NW4);
    cvt_tf32<<<NW4 / 256, blk>>>((const float4*)wo_w, (float4*)gWo, NW4);

    // projections
    gemm_mma2<<<dim3(8, 32), blk, GEMM_SMEM>>>(gXq, gWq, wq_b, gQ, NQ, 1);
    gemm_mma2<<<dim3(8, 64), blk, GEMM_SMEM>>>(gXk, gWk, wk_b, gK, NK, 1);
    gemm_mma2<<<dim3(8, 64), blk, GEMM_SMEM>>>(gXv, gWv, wv_b, gV, NK, 1);

    // attention
    attn4<<<BATCH * HEADS * (NQ / 128), blk, ATTN_SMEM>>>(gQ, gK, gV, mult, gA);

    // output projection
    gemm_mma2<<<dim3(8, 32), blk, GEMM_SMEM>>>(gA, gWo, wo_b, out, NQ, 0);
}

// round 11
// speedup vs baseline: 18.2672x; 1.9743x over previous
#include <cuda_runtime.h>
#include <cuda_fp16.h>
#include <cstdint>
#include <math.h>

#define EMBED 1024
#define HEADS 16
#define HDIM  64
#define BATCH 4
#define NQ    1024
#define NK    2048

// Scratch (static device memory) — fp16 operands, fp32 bias path
__device__ __half g_Q[(size_t)BATCH * HEADS * NQ * HDIM];   // (b,h,nq,d)
__device__ __half g_K[(size_t)BATCH * HEADS * NK * HDIM];   // (b,h,nk,d)
__device__ __half g_V[(size_t)BATCH * HEADS * NK * HDIM];   // (b,h,nk,d)
__device__ __half g_A[(size_t)BATCH * NQ * EMBED];          // (b,nq,e)
__device__ __half g_Xq[(size_t)BATCH * NQ * EMBED];
__device__ __half g_Xk[(size_t)BATCH * NK * EMBED];
__device__ __half g_Xv[(size_t)BATCH * NK * EMBED];
__device__ __half g_Wq[(size_t)EMBED * EMBED];
__device__ __half g_Wk[(size_t)EMBED * EMBED];
__device__ __half g_Wv[(size_t)EMBED * EMBED];
__device__ __half g_Wo[(size_t)EMBED * EMBED];

__device__ __forceinline__ uint32_t smem_u32(const void* p) {
    return (uint32_t)__cvta_generic_to_shared(p);
}
__device__ __forceinline__ uint32_t packh2(float a, float b) {
    __half2 h = __floats2half2_rn(a, b);
    return *(uint32_t*)&h;
}

#define CP_ASYNC16(dst_u32, src_ptr) \
    asm volatile("cp.async.cg.shared.global [%0], [%1], 16;" :: "r"(dst_u32), "l"(src_ptr))
#define CP_COMMIT() asm volatile("cp.async.commit_group;")
#define CP_WAIT1()  asm volatile("cp.async.wait_group 1;")

__device__ __forceinline__ void mma_f16(float* c, const uint32_t* a, const uint32_t* b) {
    asm volatile(
        "mma.sync.aligned.m16n8k16.row.col.f32.f16.f16.f32 "
        "{%0,%1,%2,%3}, {%4,%5,%6,%7}, {%8,%9}, {%0,%1,%2,%3};"
        : "+f"(c[0]), "+f"(c[1]), "+f"(c[2]), "+f"(c[3])
        : "r"(a[0]), "r"(a[1]), "r"(a[2]), "r"(a[3]), "r"(b[0]), "r"(b[1]));
}

__device__ __forceinline__ void ldmatrix_x4_trans(uint32_t& r0, uint32_t& r1,
                                                  uint32_t& r2, uint32_t& r3, uint32_t addr) {
    asm volatile("ldmatrix.sync.aligned.m8n8.x4.trans.shared.b16 {%0,%1,%2,%3}, [%4];"
                 : "=r"(r0), "=r"(r1), "=r"(r2), "=r"(r3) : "r"(addr));
}

// ---------------------------------------------------------------------------
// Prepass: fp32 -> fp16 (rn). Each thread converts 8 floats.
// ---------------------------------------------------------------------------
__global__ __launch_bounds__(256)
void cvt_f16(const float4* __restrict__ src, uint4* __restrict__ dst, int n8)
{
    int i = blockIdx.x * 256 + threadIdx.x;
    if (i < n8) {
        float4 a = src[2 * i], b = src[2 * i + 1];
        uint4 o;
        o.x = packh2(a.x, a.y);
        o.y = packh2(a.z, a.w);
        o.z = packh2(b.x, b.y);
        o.w = packh2(b.z, b.w);
        dst[i] = o;
    }
}

// ---------------------------------------------------------------------------
// fp16 GEMM: out = X @ W^T + bias. CTA 128x128, BK=64, 8 warps (4m x 2n),
// cp.async double buffered. split: 0 -> fp32 out (row,1024); 1 -> fp16
// head-split (b,h,n,d).
// Smem stride 72 halves (36 words): fragment words (36r + 8ks + tq) all
// distinct mod 32 -> conflict-free.
// ---------------------------------------------------------------------------
#define GSTR 72
#define GSTRW 36
#define GSTG (128 * GSTR)    // halves per tensor per stage (9216)

__global__ __launch_bounds__(256, 2)
void gemm_f16(const __half* __restrict__ A, const __half* __restrict__ W,
              const float* __restrict__ bias, void* __restrict__ outv,
              int nP, int split)
{
    extern __shared__ __half smh[];

    const int tid = threadIdx.x;
    const int wid = tid >> 5;
    const int lane = tid & 31;
    const int g = lane >> 2;
    const int tq = lane & 3;
    const int wm = wid & 3;
    const int wn = wid >> 2;
    const int row0 = blockIdx.y * 128;
    const int col0 = blockIdx.x * 128;

    float c[2][8][4];
#pragma unroll
    for (int mt = 0; mt < 2; mt++)
#pragma unroll
        for (int nt = 0; nt < 8; nt++)
#pragma unroll
            for (int i = 0; i < 4; i++) c[mt][nt][i] = 0.f;

    auto load_stage = [&](int s, int k0) {
        __half* As = smh + s * 2 * GSTG;
        __half* Bs = As + GSTG;
#pragma unroll
        for (int i = 0; i < 4; i++) {
            int f = tid + i * 256;
            int r = f >> 3, cc = f & 7;
            CP_ASYNC16(smem_u32(&As[r * GSTR + cc * 8]),
                       A + (size_t)(row0 + r) * EMBED + k0 + cc * 8);
            CP_ASYNC16(smem_u32(&Bs[r * GSTR + cc * 8]),
                       W + (size_t)(col0 + r) * EMBED + k0 + cc * 8);
        }
    };

    load_stage(0, 0);  CP_COMMIT();
    load_stage(1, 64); CP_COMMIT();

    for (int it = 0; it < 16; it++) {
        CP_WAIT1();
        __syncthreads();
        const uint32_t* Asu = (const uint32_t*)(smh + (it & 1) * 2 * GSTG);
        const uint32_t* Bsu = Asu + GSTG / 2;

#pragma unroll
        for (int ks = 0; ks < 4; ks++) {
            uint32_t a[2][4];
#pragma unroll
            for (int mt = 0; mt < 2; mt++) {
                int rb = wm * 32 + mt * 16;
                a[mt][0] = Asu[(rb + g) * GSTRW + 8 * ks + tq];
                a[mt][1] = Asu[(rb + g + 8) * GSTRW + 8 * ks + tq];
                a[mt][2] = Asu[(rb + g) * GSTRW + 8 * ks + tq + 4];
                a[mt][3] = Asu[(rb + g + 8) * GSTRW + 8 * ks + tq + 4];
            }
#pragma unroll
            for (int nt = 0; nt < 8; nt++) {
                int nb = wn * 64 + nt * 8;
                uint32_t b[2];
                b[0] = Bsu[(nb + g) * GSTRW + 8 * ks + tq];
                b[1] = Bsu[(nb + g) * GSTRW + 8 * ks + tq + 4];
#pragma unroll
                for (int mt = 0; mt < 2; mt++)
                    mma_f16(c[mt][nt], a[mt], b);
            }
        }
        __syncthreads();
        if (it + 2 < 16) load_stage(it & 1, (it + 2) * 64);
        CP_COMMIT();
    }

    // epilogue
#pragma unroll
    for (int mt = 0; mt < 2; mt++) {
#pragma unroll
        for (int half_ = 0; half_ < 2; half_++) {
            int grow = row0 + wm * 32 + mt * 16 + g + half_ * 8;
            int bb = grow / nP, n = grow - bb * nP;
#pragma unroll
            for (int nt = 0; nt < 8; nt++) {
                int gcol = col0 + wn * 64 + nt * 8 + tq * 2;
                float v0 = c[mt][nt][half_ * 2 + 0] + bias[gcol];
                float v1 = c[mt][nt][half_ * 2 + 1] + bias[gcol + 1];
                if (split == 1) {
                    int h = gcol >> 6, d = gcol & 63;
                    uint32_t* op = (uint32_t*)((__half*)outv +
                        (((size_t)bb * HEADS + h) * nP + n) * HDIM + d);
                    *op = packh2(v0, v1);
                } else {
                    float2* op = (float2*)((float*)outv + (size_t)grow * EMBED + gcol);
                    *op = make_float2(v0, v1);
                }
            }
        }
    }
}

// ---------------------------------------------------------------------------
// Attention, fp16 mma. CTA: 128 queries (8 warps x 16q), 64-key chunks,
// cp.async double-buffered K/V. P C-frag -> A-frag is free (half2 packing).
// V consumed via ldmatrix.x4.trans (transposed B-fragments).
// ---------------------------------------------------------------------------
#define ASTR 72
#define ASTRW 36
#define Q_HALVES (128 * ASTR)      // 9216
#define KV_HALVES (64 * ASTR)      // 4608 per tensor

__global__ __launch_bounds__(256, 2)
void attn5(const __half* __restrict__ Q, const __half* __restrict__ K,
           const __half* __restrict__ V, const float* __restrict__ mult,
           __half* __restrict__ Out)
{
    extern __shared__ __half sh[];
    __half* Qs = sh;   // 128 x 72
    // stage s: Ks = sh + 9216 + s*9216, Vs = Ks + 4608

    const int tid  = threadIdx.x;
    const int w    = tid >> 5;
    const int lane = tid & 31;
    const int g    = lane >> 2;
    const int tq   = lane & 3;
    const int bx = blockIdx.x;
    const int q0 = (bx & 7) * 128;
    const int h  = (bx >> 3) & 15;
    const int b  = bx >> 7;

    const __half* Qbase = Q + (((size_t)(b * HEADS + h) * NQ) + q0) * HDIM;
    const __half* Kbase = K + ((size_t)(b * HEADS + h) * NK) * HDIM;
    const __half* Vbase = V + ((size_t)(b * HEADS + h) * NK) * HDIM;
    const float* mbase = mult + (size_t)b * NK;

    // Q tile 128x64 halves (1024 x 16B chunks -> 4/thread)
#pragma unroll
    for (int i = 0; i < 4; i++) {
        int f = tid + i * 256;
        int r = f >> 3, cc = f & 7;
        CP_ASYNC16(smem_u32(&Qs[r * ASTR + cc * 8]),
                   Qbase + (size_t)r * HDIM + cc * 8);
    }
    CP_COMMIT();

    auto load_kv = [&](int s, int c0) {
        __half* Ks = sh + Q_HALVES + s * 2 * KV_HALVES;
        __half* Vs = Ks + KV_HALVES;
#pragma unroll
        for (int i = 0; i < 2; i++) {
            int f = tid + i * 256;
            int r = f >> 3, cc = f & 7;
            CP_ASYNC16(smem_u32(&Ks[r * ASTR + cc * 8]),
                       Kbase + (size_t)(c0 + r) * HDIM + cc * 8);
            CP_ASYNC16(smem_u32(&Vs[r * ASTR + cc * 8]),
                       Vbase + (size_t)(c0 + r) * HDIM + cc * 8);
        }
    };

    load_kv(0, 0);  CP_COMMIT();
    load_kv(1, 64); CP_COMMIT();

    const int qb = w * 16;
    // per-lane static part of ldmatrix.trans address (halves)
    const int mi = lane >> 3, rl = lane & 7;
    const uint32_t vlane_off = (uint32_t)((rl + 8 * (mi & 1)) * ASTR + 8 * (mi >> 1));

    float m0 = -INFINITY, m1 = -INFINITY, l0 = 0.f, l1 = 0.f;
    float Oc[8][4];
#pragma unroll
    for (int dt = 0; dt < 8; dt++)
#pragma unroll
        for (int i = 0; i < 4; i++) Oc[dt][i] = 0.f;

    for (int c0 = 0; c0 < NK; c0 += 64) {
        const int stg = (c0 >> 6) & 1;
        float2 mv = *(const float2*)(mbase + c0 + 2 * lane);
        float lm0 = __logf(mv.x);
        float lm1 = __logf(mv.y);

        CP_WAIT1();
        __syncthreads();
        const __half* Ksh = sh + Q_HALVES + stg * 2 * KV_HALVES;
        const uint32_t* Ksu = (const uint32_t*)Ksh;
        const uint32_t vbase = smem_u32(Ksh + KV_HALVES) + vlane_off * 2;
        const uint32_t* Qsu = (const uint32_t*)Qs;

        // ---- S = Q K^T ----
        float Sc[8][4];
#pragma unroll
        for (int nt = 0; nt < 8; nt++)
#pragma unroll
            for (int i = 0; i < 4; i++) Sc[nt][i] = 0.f;

#pragma unroll
        for (int ks = 0; ks < 4; ks++) {
            uint32_t a[4];
            a[0] = Qsu[(qb + g) * ASTRW + 8 * ks + tq];
            a[1] = Qsu[(qb + g + 8) * ASTRW + 8 * ks + tq];
            a[2] = Qsu[(qb + g) * ASTRW + 8 * ks + tq + 4];
            a[3] = Qsu[(qb + g + 8) * ASTRW + 8 * ks + tq + 4];
#pragma unroll
            for (int nt = 0; nt < 8; nt++) {
                uint32_t bfr[2];
                bfr[0] = Ksu[(nt * 8 + g) * ASTRW + 8 * ks + tq];
                bfr[1] = Ksu[(nt * 8 + g) * ASTRW + 8 * ks + tq + 4];
                mma_f16(Sc[nt], a, bfr);
            }
        }

        // ---- softmax ----
        float rmax0 = -INFINITY, rmax1 = -INFINITY;
#pragma unroll
        for (int nt = 0; nt < 8; nt++) {
            float lmA = __shfl_sync(0xffffffffu, lm0, nt * 4 + tq);
            float lmB = __shfl_sync(0xffffffffu, lm1, nt * 4 + tq);
            Sc[nt][0] = Sc[nt][0] * 0.125f + lmA;
            Sc[nt][1] = Sc[nt][1] * 0.125f + lmB;
            Sc[nt][2] = Sc[nt][2] * 0.125f + lmA;
            Sc[nt][3] = Sc[nt][3] * 0.125f + lmB;
            rmax0 = fmaxf(rmax0, fmaxf(Sc[nt][0], Sc[nt][1]));
            rmax1 = fmaxf(rmax1, fmaxf(Sc[nt][2], Sc[nt][3]));
        }
        rmax0 = fmaxf(rmax0, __shfl_xor_sync(0xffffffffu, rmax0, 1));
        rmax0 = fmaxf(rmax0, __shfl_xor_sync(0xffffffffu, rmax0, 2));
        rmax1 = fmaxf(rmax1, __shfl_xor_sync(0xffffffffu, rmax1, 1));
        rmax1 = fmaxf(rmax1, __shfl_xor_sync(0xffffffffu, rmax1, 2));

        float mn0 = fmaxf(m0, rmax0);
        float mn1 = fmaxf(m1, rmax1);
        float alpha0 = __expf(m0 - mn0);
        float alpha1 = __expf(m1 - mn1);
        m0 = mn0; m1 = mn1;

        float ls0 = 0.f, ls1 = 0.f;
#pragma unroll
        for (int nt = 0; nt < 8; nt++) {
            Sc[nt][0] = __expf(Sc[nt][0] - mn0);
            Sc[nt][1] = __expf(Sc[nt][1] - mn0);
            Sc[nt][2] = __expf(Sc[nt][2] - mn1);
            Sc[nt][3] = __expf(Sc[nt][3] - mn1);
            ls0 += Sc[nt][0] + Sc[nt][1];
            ls1 += Sc[nt][2] + Sc[nt][3];
        }
        ls0 += __shfl_xor_sync(0xffffffffu, ls0, 1);
        ls0 += __shfl_xor_sync(0xffffffffu, ls0, 2);
        ls1 += __shfl_xor_sync(0xffffffffu, ls1, 1);
        ls1 += __shfl_xor_sync(0xffffffffu, ls1, 2);
        l0 = l0 * alpha0 + ls0;
        l1 = l1 * alpha1 + ls1;

#pragma unroll
        for (int dt = 0; dt < 8; dt++) {
            Oc[dt][0] *= alpha0; Oc[dt][1] *= alpha0;
            Oc[dt][2] *= alpha1; Oc[dt][3] *= alpha1;
        }

        // ---- P: pack C-frags into fp16 A-frags (free; no shuffles) ----
        uint32_t Pa[4][4];
#pragma unroll
        for (int j = 0; j < 4; j++) {
            Pa[j][0] = packh2(Sc[2 * j][0],     Sc[2 * j][1]);
            Pa[j][1] = packh2(Sc[2 * j][2],     Sc[2 * j][3]);
            Pa[j][2] = packh2(Sc[2 * j + 1][0], Sc[2 * j + 1][1]);
            Pa[j][3] = packh2(Sc[2 * j + 1][2], Sc[2 * j + 1][3]);
        }

        // ---- O += P V via ldmatrix.trans B-fragments ----
#pragma unroll
        for (int j = 0; j < 4; j++) {
            const uint32_t abase = vbase + j * (16 * ASTR * 2);
#pragma unroll
            for (int dtp = 0; dtp < 4; dtp++) {
                uint32_t r0, r1, r2, r3;
                ldmatrix_x4_trans(r0, r1, r2, r3, abase + dtp * 32);
                uint32_t blo[2] = {r0, r1};
                uint32_t bhi[2] = {r2, r3};
                mma_f16(Oc[2 * dtp],     Pa[j], blo);
                mma_f16(Oc[2 * dtp + 1], Pa[j], bhi);
            }
        }

        __syncthreads();
        if (c0 + 128 < NK) load_kv(stg, c0 + 128);
        CP_COMMIT();
    }

    // ---- write out fp16 (b, q, h*64 + d) ----
    const float inv0 = 1.f / l0;
    const float inv1 = 1.f / l1;
    const int qg0 = q0 + qb + g;
    __half* o0 = Out + ((size_t)(b * NQ + qg0)) * EMBED + h * HDIM;
    __half* o1 = o0 + (size_t)8 * EMBED;
#pragma unroll
    for (int dt = 0; dt < 8; dt++) {
        int col = dt * 8 + 2 * tq;
        *(uint32_t*)(o0 + col) = packh2(Oc[dt][0] * inv0, Oc[dt][1] * inv0);
        *(uint32_t*)(o1 + col) = packh2(Oc[dt][2] * inv1, Oc[dt][3] * inv1);
    }
}

// ---------------------------------------------------------------------------
// launch
// ---------------------------------------------------------------------------
extern "C" void kernel_launch(void* const* d_in, const int* in_sizes, int n_in,
                              void* d_out, int out_size)
{
    const float* query = (const float*)d_in[0];
    const float* key   = (const float*)d_in[1];
    const float* value = (const float*)d_in[2];
    const float* mult  = (const float*)d_in[3];
    const float* wq_w  = (const float*)d_in[4];
    const float* wq_b  = (const float*)d_in[5];
    const float* wk_w  = (const float*)d_in[6];
    const float* wk_b  = (const float*)d_in[7];
    const float* wv_w  = (const float*)d_in[8];
    const float* wv_b  = (const float*)d_in[9];
    const float* wo_w  = (const float*)d_in[10];
    const float* wo_b  = (const float*)d_in[11];
    float* out = (float*)d_out;

    __half *gQ, *gK, *gV, *gA, *gXq, *gXk, *gXv, *gWq, *gWk, *gWv, *gWo;
    cudaGetSymbolAddress((void**)&gQ, g_Q);
    cudaGetSymbolAddress((void**)&gK, g_K);
    cudaGetSymbolAddress((void**)&gV, g_V);
    cudaGetSymbolAddress((void**)&gA, g_A);
    cudaGetSymbolAddress((void**)&gXq, g_Xq);
    cudaGetSymbolAddress((void**)&gXk, g_Xk);
    cudaGetSymbolAddress((void**)&gXv, g_Xv);
    cudaGetSymbolAddress((void**)&gWq, g_Wq);
    cudaGetSymbolAddress((void**)&gWk, g_Wk);
    cudaGetSymbolAddress((void**)&gWv, g_Wv);
    cudaGetSymbolAddress((void**)&gWo, g_Wo);

    const int GEMM_SMEM = 2 * 2 * GSTG * 2;                    // 73728
    const int ATTN_SMEM = (Q_HALVES + 2 * 2 * KV_HALVES) * 2;  // 55296
    cudaFuncSetAttribute(gemm_f16, cudaFuncAttributeMaxDynamicSharedMemorySize, GEMM_SMEM);
    cudaFuncSetAttribute(attn5, cudaFuncAttributeMaxDynamicSharedMemorySize, ATTN_SMEM);

    dim3 blk(256);
    // fp16 prepass
    const int NQ8 = BATCH * NQ * EMBED / 8;   // 524288
    const int NK8 = BATCH * NK * EMBED / 8;   // 1048576
    const int NW8 = EMBED * EMBED / 8;        // 131072
    cvt_f16<<<NQ8 / 256, blk>>>((const float4*)query, (uint4*)gXq, NQ8);
    cvt_f16<<<NK8 / 256, blk>>>((const float4*)key,   (uint4*)gXk, NK8);
    cvt_f16<<<NK8 / 256, blk>>>((const float4*)value, (uint4*)gXv, NK8);
    cvt_f16<<<NW8 / 256, blk>>>((const float4*)wq_w, (uint4*)gWq, NW8);
    cvt_f16<<<NW8 / 256, blk>>>((const float4*)wk_w, (uint4*)gWk, NW8);
    cvt_f16<<<NW8 / 256, blk>>>((const float4*)wv_w, (uint4*)gWv, NW8);
    cvt_f16<<<NW8 / 256, blk>>>((const float4*)wo_w, (uint4*)gWo, NW8);

    // projections (fp16 mma)
    gemm_f16<<<dim3(8, 32), blk, GEMM_SMEM>>>(gXq, gWq, wq_b, gQ, NQ, 1);
    gemm_f16<<<dim3(8, 64), blk, GEMM_SMEM>>>(gXk, gWk, wk_b, gK, NK, 1);
    gemm_f16<<<dim3(8, 64), blk, GEMM_SMEM>>>(gXv, gWv, wv_b, gV, NK, 1);

    // attention
    attn5<<<BATCH * HEADS * (NQ / 128), blk, ATTN_SMEM>>>(gQ, gK, gV, mult, gA);

    // output projection (fp32 out)
    gemm_f16<<<dim3(8, 32), blk, GEMM_SMEM>>>(gA, gWo, wo_b, out, NQ, 0);
}

// round 12
// speedup vs baseline: 19.6379x; 1.0750x over previous
#include <cuda_runtime.h>
#include <cuda_fp16.h>
#include <cstdint>
#include <math.h>

#define EMBED 1024
#define HEADS 16
#define HDIM  64
#define BATCH 4
#define NQ    1024
#define NK    2048

// Scratch (static device memory) — fp16 operands
__device__ __half g_Q[(size_t)BATCH * HEADS * NQ * HDIM];
__device__ __half g_K[(size_t)BATCH * HEADS * NK * HDIM];
__device__ __half g_V[(size_t)BATCH * HEADS * NK * HDIM];
__device__ __half g_A[(size_t)BATCH * NQ * EMBED];
__device__ __half g_Xq[(size_t)BATCH * NQ * EMBED];
__device__ __half g_Xk[(size_t)BATCH * NK * EMBED];
__device__ __half g_Xv[(size_t)BATCH * NK * EMBED];
__device__ __half g_Wq[(size_t)EMBED * EMBED];
__device__ __half g_Wk[(size_t)EMBED * EMBED];
__device__ __half g_Wv[(size_t)EMBED * EMBED];
__device__ __half g_Wo[(size_t)EMBED * EMBED];

__device__ __forceinline__ uint32_t smem_u32(const void* p) {
    return (uint32_t)__cvta_generic_to_shared(p);
}
__device__ __forceinline__ uint32_t packh2(float a, float b) {
    __half2 h = __floats2half2_rn(a, b);
    return *(uint32_t*)&h;
}

#define CP_ASYNC16(dst_u32, src_ptr) \
    asm volatile("cp.async.cg.shared.global [%0], [%1], 16;" :: "r"(dst_u32), "l"(src_ptr))
#define CP_COMMIT() asm volatile("cp.async.commit_group;")
#define CP_WAIT1()  asm volatile("cp.async.wait_group 1;")

__device__ __forceinline__ void mma_f16(float* c, const uint32_t* a, const uint32_t* b) {
    asm volatile(
        "mma.sync.aligned.m16n8k16.row.col.f32.f16.f16.f32 "
        "{%0,%1,%2,%3}, {%4,%5,%6,%7}, {%8,%9}, {%0,%1,%2,%3};"
        : "+f"(c[0]), "+f"(c[1]), "+f"(c[2]), "+f"(c[3])
        : "r"(a[0]), "r"(a[1]), "r"(a[2]), "r"(a[3]), "r"(b[0]), "r"(b[1]));
}
__device__ __forceinline__ void ldmx4(uint32_t& r0, uint32_t& r1, uint32_t& r2, uint32_t& r3,
                                      uint32_t addr) {
    asm volatile("ldmatrix.sync.aligned.m8n8.x4.shared.b16 {%0,%1,%2,%3}, [%4];"
                 : "=r"(r0), "=r"(r1), "=r"(r2), "=r"(r3) : "r"(addr));
}
__device__ __forceinline__ void ldmx4_trans(uint32_t& r0, uint32_t& r1, uint32_t& r2, uint32_t& r3,
                                            uint32_t addr) {
    asm volatile("ldmatrix.sync.aligned.m8n8.x4.trans.shared.b16 {%0,%1,%2,%3}, [%4];"
                 : "=r"(r0), "=r"(r1), "=r"(r2), "=r"(r3) : "r"(addr));
}

// ---------------------------------------------------------------------------
// Fused prepass: fp32 -> fp16 for all 7 tensors in one launch.
// Block b handles 2048 elems of segment chosen by block range.
// ---------------------------------------------------------------------------
__global__ __launch_bounds__(256)
void cvt_all(const float4* sXq, uint4* dXq, const float4* sXk, uint4* dXk,
             const float4* sXv, uint4* dXv, const float4* sWq, uint4* dWq,
             const float4* sWk, uint4* dWk, const float4* sWv, uint4* dWv,
             const float4* sWo, uint4* dWo)
{
    int blk = blockIdx.x;
    const float4* src;
    uint4* dst;
    int base;
    if (blk < 2048)       { src = sXq; dst = dXq; base = blk; }
    else if (blk < 6144)  { src = sXk; dst = dXk; base = blk - 2048; }
    else if (blk < 10240) { src = sXv; dst = dXv; base = blk - 6144; }
    else if (blk < 10752) { src = sWq; dst = dWq; base = blk - 10240; }
    else if (blk < 11264) { src = sWk; dst = dWk; base = blk - 10752; }
    else if (blk < 11776) { src = sWv; dst = dWv; base = blk - 11264; }
    else                  { src = sWo; dst = dWo; base = blk - 11776; }
    int i = base * 256 + threadIdx.x;
    float4 a = src[2 * i], b = src[2 * i + 1];
    uint4 o;
    o.x = packh2(a.x, a.y);
    o.y = packh2(a.z, a.w);
    o.z = packh2(b.x, b.y);
    o.w = packh2(b.z, b.w);
    dst[i] = o;
}

// ---------------------------------------------------------------------------
// fp16 GEMM: out = X @ W^T + bias. CTA 128x128, BK=64, 8 warps (4m x 2n),
// cp.async double buffered, ldmatrix fragment loads.
// ---------------------------------------------------------------------------
#define GSTR 72
#define GSTG (128 * GSTR)    // halves per tensor per stage

__global__ __launch_bounds__(256, 2)
void gemm_f16(const __half* __restrict__ A, const __half* __restrict__ W,
              const float* __restrict__ bias, void* __restrict__ outv,
              int nP, int split)
{
    extern __shared__ __half smh[];

    const int tid = threadIdx.x;
    const int wid = tid >> 5;
    const int lane = tid & 31;
    const int g = lane >> 2;
    const int tq = lane & 3;
    const int wm = wid & 3;
    const int wn = wid >> 2;
    const int row0 = blockIdx.y * 128;
    const int col0 = blockIdx.x * 128;

    // ldmatrix per-lane offsets (in bytes)
    const uint32_t aoff = (uint32_t)((((lane & 7) + ((lane >> 3) & 1) * 8) * GSTR
                                      + ((lane >> 4) & 1) * 8) * 2);
    const uint32_t boff = (uint32_t)((((lane & 7) + ((lane >> 4) & 1) * 8) * GSTR
                                      + ((lane >> 3) & 1) * 8) * 2);

    float c[2][8][4];
#pragma unroll
    for (int mt = 0; mt < 2; mt++)
#pragma unroll
        for (int nt = 0; nt < 8; nt++)
#pragma unroll
            for (int i = 0; i < 4; i++) c[mt][nt][i] = 0.f;

    auto load_stage = [&](int s, int k0) {
        __half* As = smh + s * 2 * GSTG;
        __half* Bs = As + GSTG;
#pragma unroll
        for (int i = 0; i < 4; i++) {
            int f = tid + i * 256;
            int r = f >> 3, cc = f & 7;
            CP_ASYNC16(smem_u32(&As[r * GSTR + cc * 8]),
                       A + (size_t)(row0 + r) * EMBED + k0 + cc * 8);
            CP_ASYNC16(smem_u32(&Bs[r * GSTR + cc * 8]),
                       W + (size_t)(col0 + r) * EMBED + k0 + cc * 8);
        }
    };

    load_stage(0, 0);  CP_COMMIT();
    load_stage(1, 64); CP_COMMIT();

    for (int it = 0; it < 16; it++) {
        CP_WAIT1();
        __syncthreads();
        const __half* As = smh + (it & 1) * 2 * GSTG;
        const uint32_t Abase = smem_u32(As) + aoff;
        const uint32_t Bbase = smem_u32(As + GSTG) + boff;

#pragma unroll
        for (int ks = 0; ks < 4; ks++) {
            uint32_t a[2][4];
#pragma unroll
            for (int mt = 0; mt < 2; mt++)
                ldmx4(a[mt][0], a[mt][1], a[mt][2], a[mt][3],
                      Abase + (uint32_t)(((wm * 32 + mt * 16) * GSTR + ks * 16) * 2));
#pragma unroll
            for (int ntp = 0; ntp < 4; ntp++) {
                uint32_t b0, b1, b2, b3;
                ldmx4(b0, b1, b2, b3,
                      Bbase + (uint32_t)(((wn * 64 + ntp * 16) * GSTR + ks * 16) * 2));
                uint32_t blo[2] = {b0, b1};
                uint32_t bhi[2] = {b2, b3};
#pragma unroll
                for (int mt = 0; mt < 2; mt++) {
                    mma_f16(c[mt][2 * ntp], a[mt], blo);
                    mma_f16(c[mt][2 * ntp + 1], a[mt], bhi);
                }
            }
        }
        __syncthreads();
        if (it + 2 < 16) load_stage(it & 1, (it + 2) * 64);
        CP_COMMIT();
    }

    // epilogue
#pragma unroll
    for (int mt = 0; mt < 2; mt++) {
#pragma unroll
        for (int half_ = 0; half_ < 2; half_++) {
            int grow = row0 + wm * 32 + mt * 16 + g + half_ * 8;
            int bb = grow / nP, n = grow - bb * nP;
#pragma unroll
            for (int nt = 0; nt < 8; nt++) {
                int gcol = col0 + wn * 64 + nt * 8 + tq * 2;
                float v0 = c[mt][nt][half_ * 2 + 0] + bias[gcol];
                float v1 = c[mt][nt][half_ * 2 + 1] + bias[gcol + 1];
                if (split == 1) {
                    int h = gcol >> 6, d = gcol & 63;
                    uint32_t* op = (uint32_t*)((__half*)outv +
                        (((size_t)bb * HEADS + h) * nP + n) * HDIM + d);
                    *op = packh2(v0, v1);
                } else {
                    float2* op = (float2*)((float*)outv + (size_t)grow * EMBED + gcol);
                    *op = make_float2(v0, v1);
                }
            }
        }
    }
}

// ---------------------------------------------------------------------------
// Attention, fp16 mma + ldmatrix everywhere. CTA: 128 q (8 warps x 16q),
// 64-key chunks, cp.async double-buffered K/V.
// ---------------------------------------------------------------------------
#define ASTR 72
#define Q_HALVES (128 * ASTR)
#define KV_HALVES (64 * ASTR)

__global__ __launch_bounds__(256, 2)
void attn5(const __half* __restrict__ Q, const __half* __restrict__ K,
           const __half* __restrict__ V, const float* __restrict__ mult,
           __half* __restrict__ Out)
{
    extern __shared__ __half sh[];
    __half* Qs = sh;

    const int tid  = threadIdx.x;
    const int w    = tid >> 5;
    const int lane = tid & 31;
    const int g    = lane >> 2;
    const int tq   = lane & 3;
    const int bx = blockIdx.x;
    const int q0 = (bx & 7) * 128;
    const int h  = (bx >> 3) & 15;
    const int b  = bx >> 7;

    const __half* Qbase = Q + (((size_t)(b * HEADS + h) * NQ) + q0) * HDIM;
    const __half* Kbase = K + ((size_t)(b * HEADS + h) * NK) * HDIM;
    const __half* Vbase = V + ((size_t)(b * HEADS + h) * NK) * HDIM;
    const float* mbase = mult + (size_t)b * NK;

#pragma unroll
    for (int i = 0; i < 4; i++) {
        int f = tid + i * 256;
        int r = f >> 3, cc = f & 7;
        CP_ASYNC16(smem_u32(&Qs[r * ASTR + cc * 8]),
                   Qbase + (size_t)r * HDIM + cc * 8);
    }
    CP_COMMIT();

    auto load_kv = [&](int s, int c0) {
        __half* Ks = sh + Q_HALVES + s * 2 * KV_HALVES;
        __half* Vs = Ks + KV_HALVES;
#pragma unroll
        for (int i = 0; i < 2; i++) {
            int f = tid + i * 256;
            int r = f >> 3, cc = f & 7;
            CP_ASYNC16(smem_u32(&Ks[r * ASTR + cc * 8]),
                       Kbase + (size_t)(c0 + r) * HDIM + cc * 8);
            CP_ASYNC16(smem_u32(&Vs[r * ASTR + cc * 8]),
                       Vbase + (size_t)(c0 + r) * HDIM + cc * 8);
        }
    };

    load_kv(0, 0);  CP_COMMIT();
    load_kv(1, 64); CP_COMMIT();

    const int qb = w * 16;
    const uint32_t aoff = (uint32_t)((((lane & 7) + ((lane >> 3) & 1) * 8) * ASTR
                                      + ((lane >> 4) & 1) * 8) * 2);
    const uint32_t boff = (uint32_t)((((lane & 7) + ((lane >> 4) & 1) * 8) * ASTR
                                      + ((lane >> 3) & 1) * 8) * 2);
    // V trans-ldmatrix lane offset (halves)
    const int mi = lane >> 3, rl = lane & 7;
    const uint32_t vlane_off = (uint32_t)((rl + 8 * (mi & 1)) * ASTR + 8 * (mi >> 1));

    float m0 = -INFINITY, m1 = -INFINITY, l0 = 0.f, l1 = 0.f;
    float Oc[8][4];
#pragma unroll
    for (int dt = 0; dt < 8; dt++)
#pragma unroll
        for (int i = 0; i < 4; i++) Oc[dt][i] = 0.f;

    const uint32_t Qsb = smem_u32(Qs) + aoff + (uint32_t)(qb * ASTR * 2);

    for (int c0 = 0; c0 < NK; c0 += 64) {
        const int stg = (c0 >> 6) & 1;
        float2 mv = *(const float2*)(mbase + c0 + 2 * lane);
        float lm0 = __logf(mv.x);
        float lm1 = __logf(mv.y);

        CP_WAIT1();
        __syncthreads();
        const __half* Ksh = sh + Q_HALVES + stg * 2 * KV_HALVES;
        const uint32_t Kb = smem_u32(Ksh) + boff;
        const uint32_t vbase = smem_u32(Ksh + KV_HALVES) + vlane_off * 2;

        // ---- S = Q K^T ----
        float Sc[8][4];
#pragma unroll
        for (int nt = 0; nt < 8; nt++)
#pragma unroll
            for (int i = 0; i < 4; i++) Sc[nt][i] = 0.f;

#pragma unroll
        for (int ks = 0; ks < 4; ks++) {
            uint32_t a[4];
            ldmx4(a[0], a[1], a[2], a[3], Qsb + (uint32_t)(ks * 32));
#pragma unroll
            for (int ntp = 0; ntp < 4; ntp++) {
                uint32_t b0, b1, b2, b3;
                ldmx4(b0, b1, b2, b3,
                      Kb + (uint32_t)((ntp * 16 * ASTR + ks * 16) * 2));
                uint32_t blo[2] = {b0, b1};
                uint32_t bhi[2] = {b2, b3};
                mma_f16(Sc[2 * ntp], a, blo);
                mma_f16(Sc[2 * ntp + 1], a, bhi);
            }
        }

        // ---- softmax ----
        float rmax0 = -INFINITY, rmax1 = -INFINITY;
#pragma unroll
        for (int nt = 0; nt < 8; nt++) {
            float lmA = __shfl_sync(0xffffffffu, lm0, nt * 4 + tq);
            float lmB = __shfl_sync(0xffffffffu, lm1, nt * 4 + tq);
            Sc[nt][0] = Sc[nt][0] * 0.125f + lmA;
            Sc[nt][1] = Sc[nt][1] * 0.125f + lmB;
            Sc[nt][2] = Sc[nt][2] * 0.125f + lmA;
            Sc[nt][3] = Sc[nt][3] * 0.125f + lmB;
            rmax0 = fmaxf(rmax0, fmaxf(Sc[nt][0], Sc[nt][1]));
            rmax1 = fmaxf(rmax1, fmaxf(Sc[nt][2], Sc[nt][3]));
        }
        rmax0 = fmaxf(rmax0, __shfl_xor_sync(0xffffffffu, rmax0, 1));
        rmax0 = fmaxf(rmax0, __shfl_xor_sync(0xffffffffu, rmax0, 2));
        rmax1 = fmaxf(rmax1, __shfl_xor_sync(0xffffffffu, rmax1, 1));
        rmax1 = fmaxf(rmax1, __shfl_xor_sync(0xffffffffu, rmax1, 2));

        float mn0 = fmaxf(m0, rmax0);
        float mn1 = fmaxf(m1, rmax1);
        float alpha0 = __expf(m0 - mn0);
        float alpha1 = __expf(m1 - mn1);
        m0 = mn0; m1 = mn1;

        float ls0 = 0.f, ls1 = 0.f;
#pragma unroll
        for (int nt = 0; nt < 8; nt++) {
            Sc[nt][0] = __expf(Sc[nt][0] - mn0);
            Sc[nt][1] = __expf(Sc[nt][1] - mn0);
            Sc[nt][2] = __expf(Sc[nt][2] - mn1);
            Sc[nt][3] = __expf(Sc[nt][3] - mn1);
            ls0 += Sc[nt][0] + Sc[nt][1];
            ls1 += Sc[nt][2] + Sc[nt][3];
        }
        ls0 += __shfl_xor_sync(0xffffffffu, ls0, 1);
        ls0 += __shfl_xor_sync(0xffffffffu, ls0, 2);
        ls1 += __shfl_xor_sync(0xffffffffu, ls1, 1);
        ls1 += __shfl_xor_sync(0xffffffffu, ls1, 2);
        l0 = l0 * alpha0 + ls0;
        l1 = l1 * alpha1 + ls1;

#pragma unroll
        for (int dt = 0; dt < 8; dt++) {
            Oc[dt][0] *= alpha0; Oc[dt][1] *= alpha0;
            Oc[dt][2] *= alpha1; Oc[dt][3] *= alpha1;
        }

        // ---- P C-frags -> fp16 A-frags (free packing) ----
        uint32_t Pa[4][4];
#pragma unroll
        for (int j = 0; j < 4; j++) {
            Pa[j][0] = packh2(Sc[2 * j][0],     Sc[2 * j][1]);
            Pa[j][1] = packh2(Sc[2 * j][2],     Sc[2 * j][3]);
            Pa[j][2] = packh2(Sc[2 * j + 1][0], Sc[2 * j + 1][1]);
            Pa[j][3] = packh2(Sc[2 * j + 1][2], Sc[2 * j + 1][3]);
        }

        // ---- O += P V (trans ldmatrix B-frags) ----
#pragma unroll
        for (int j = 0; j < 4; j++) {
            const uint32_t abase = vbase + j * (16 * ASTR * 2);
#pragma unroll
            for (int dtp = 0; dtp < 4; dtp++) {
                uint32_t r0, r1, r2, r3;
                ldmx4_trans(r0, r1, r2, r3, abase + dtp * 32);
                uint32_t blo[2] = {r0, r1};
                uint32_t bhi[2] = {r2, r3};
                mma_f16(Oc[2 * dtp],     Pa[j], blo);
                mma_f16(Oc[2 * dtp + 1], Pa[j], bhi);
            }
        }

        __syncthreads();
        if (c0 + 128 < NK) load_kv(stg, c0 + 128);
        CP_COMMIT();
    }

    // ---- write out fp16 ----
    const float inv0 = 1.f / l0;
    const float inv1 = 1.f / l1;
    const int qg0 = q0 + qb + g;
    __half* o0 = Out + ((size_t)(b * NQ + qg0)) * EMBED + h * HDIM;
    __half* o1 = o0 + (size_t)8 * EMBED;
#pragma unroll
    for (int dt = 0; dt < 8; dt++) {
        int col = dt * 8 + 2 * tq;
        *(uint32_t*)(o0 + col) = packh2(Oc[dt][0] * inv0, Oc[dt][1] * inv0);
        *(uint32_t*)(o1 + col) = packh2(Oc[dt][2] * inv1, Oc[dt][3] * inv1);
    }
}

// ---------------------------------------------------------------------------
// launch
// ---------------------------------------------------------------------------
extern "C" void kernel_launch(void* const* d_in, const int* in_sizes, int n_in,
                              void* d_out, int out_size)
{
    const float* query = (const float*)d_in[0];
    const float* key   = (const float*)d_in[1];
    const float* value = (const float*)d_in[2];
    const float* mult  = (const float*)d_in[3];
    const float* wq_w  = (const float*)d_in[4];
    const float* wq_b  = (const float*)d_in[5];
    const float* wk_w  = (const float*)d_in[6];
    const float* wk_b  = (const float*)d_in[7];
    const float* wv_w  = (const float*)d_in[8];
    const float* wv_b  = (const float*)d_in[9];
    const float* wo_w  = (const float*)d_in[10];
    const float* wo_b  = (const float*)d_in[11];
    float* out = (float*)d_out;

    __half *gQ, *gK, *gV, *gA, *gXq, *gXk, *gXv, *gWq, *gWk, *gWv, *gWo;
    cudaGetSymbolAddress((void**)&gQ, g_Q);
    cudaGetSymbolAddress((void**)&gK, g_K);
    cudaGetSymbolAddress((void**)&gV, g_V);
    cudaGetSymbolAddress((void**)&gA, g_A);
    cudaGetSymbolAddress((void**)&gXq, g_Xq);
    cudaGetSymbolAddress((void**)&gXk, g_Xk);
    cudaGetSymbolAddress((void**)&gXv, g_Xv);
    cudaGetSymbolAddress((void**)&gWq, g_Wq);
    cudaGetSymbolAddress((void**)&gWk, g_Wk);
    cudaGetSymbolAddress((void**)&gWv, g_Wv);
    cudaGetSymbolAddress((void**)&gWo, g_Wo);

    const int GEMM_SMEM = 2 * 2 * GSTG * 2;                    // 73728
    const int ATTN_SMEM = (Q_HALVES + 2 * 2 * KV_HALVES) * 2;  // 55296
    cudaFuncSetAttribute(gemm_f16, cudaFuncAttributeMaxDynamicSharedMemorySize, GEMM_SMEM);
    cudaFuncSetAttribute(attn5, cudaFuncAttributeMaxDynamicSharedMemorySize, ATTN_SMEM);

    dim3 blk(256);
    // fused fp16 prepass (12288 blocks)
    cvt_all<<<12288, blk>>>((const float4*)query, (uint4*)gXq,
                            (const float4*)key,   (uint4*)gXk,
                            (const float4*)value, (uint4*)gXv,
                            (const float4*)wq_w,  (uint4*)gWq,
                            (const float4*)wk_w,  (uint4*)gWk,
                            (const float4*)wv_w,  (uint4*)gWv,
                            (const float4*)wo_w,  (uint4*)gWo);

    // projections (fp16 mma)
    gemm_f16<<<dim3(8, 32), blk, GEMM_SMEM>>>(gXq, gWq, wq_b, gQ, NQ, 1);
    gemm_f16<<<dim3(8, 64), blk, GEMM_SMEM>>>(gXk, gWk, wk_b, gK, NK, 1);
    gemm_f16<<<dim3(8, 64), blk, GEMM_SMEM>>>(gXv, gWv, wv_b, gV, NK, 1);

    // attention
    attn5<<<BATCH * HEADS * (NQ / 128), blk, ATTN_SMEM>>>(gQ, gK, gV, mult, gA);

    // output projection (fp32 out)
    gemm_f16<<<dim3(8, 32), blk, GEMM_SMEM>>>(gA, gWo, wo_b, out, NQ, 0);
}

// round 13
// speedup vs baseline: 19.7741x; 1.0069x over previous
#include <cuda_runtime.h>
#include <cuda_fp16.h>
#include <cstdint>
#include <math.h>

#define EMBED 1024
#define HEADS 16
#define HDIM  64
#define BATCH 4
#define NQ    1024
#define NK    2048

// Scratch (static device memory) — fp16 operands
__device__ __half g_Q[(size_t)BATCH * HEADS * NQ * HDIM];
__device__ __half g_K[(size_t)BATCH * HEADS * NK * HDIM];
__device__ __half g_V[(size_t)BATCH * HEADS * NK * HDIM];
__device__ __half g_A[(size_t)BATCH * NQ * EMBED];
__device__ __half g_Xq[(size_t)BATCH * NQ * EMBED];
__device__ __half g_Xk[(size_t)BATCH * NK * EMBED];
__device__ __half g_Xv[(size_t)BATCH * NK * EMBED];
__device__ __half g_Wq[(size_t)EMBED * EMBED];
__device__ __half g_Wk[(size_t)EMBED * EMBED];
__device__ __half g_Wv[(size_t)EMBED * EMBED];
__device__ __half g_Wo[(size_t)EMBED * EMBED];

__device__ __forceinline__ uint32_t smem_u32(const void* p) {
    return (uint32_t)__cvta_generic_to_shared(p);
}
__device__ __forceinline__ uint32_t packh2(float a, float b) {
    __half2 h = __floats2half2_rn(a, b);
    return *(uint32_t*)&h;
}

#define CP_ASYNC16(dst_u32, src_ptr) \
    asm volatile("cp.async.cg.shared.global [%0], [%1], 16;" :: "r"(dst_u32), "l"(src_ptr))
#define CP_COMMIT() asm volatile("cp.async.commit_group;")
#define CP_WAIT1()  asm volatile("cp.async.wait_group 1;")

__device__ __forceinline__ void mma_f16(float* c, const uint32_t* a, const uint32_t* b) {
    asm volatile(
        "mma.sync.aligned.m16n8k16.row.col.f32.f16.f16.f32 "
        "{%0,%1,%2,%3}, {%4,%5,%6,%7}, {%8,%9}, {%0,%1,%2,%3};"
        : "+f"(c[0]), "+f"(c[1]), "+f"(c[2]), "+f"(c[3])
        : "r"(a[0]), "r"(a[1]), "r"(a[2]), "r"(a[3]), "r"(b[0]), "r"(b[1]));
}
__device__ __forceinline__ void ldmx4(uint32_t& r0, uint32_t& r1, uint32_t& r2, uint32_t& r3,
                                      uint32_t addr) {
    asm volatile("ldmatrix.sync.aligned.m8n8.x4.shared.b16 {%0,%1,%2,%3}, [%4];"
                 : "=r"(r0), "=r"(r1), "=r"(r2), "=r"(r3) : "r"(addr));
}
__device__ __forceinline__ void ldmx4_trans(uint32_t& r0, uint32_t& r1, uint32_t& r2, uint32_t& r3,
                                            uint32_t addr) {
    asm volatile("ldmatrix.sync.aligned.m8n8.x4.trans.shared.b16 {%0,%1,%2,%3}, [%4];"
                 : "=r"(r0), "=r"(r1), "=r"(r2), "=r"(r3) : "r"(addr));
}

// ---------------------------------------------------------------------------
// Fused prepass: fp32 -> fp16 for all 7 tensors in one launch.
// ---------------------------------------------------------------------------
__global__ __launch_bounds__(256)
void cvt_all(const float4* sXq, uint4* dXq, const float4* sXk, uint4* dXk,
             const float4* sXv, uint4* dXv, const float4* sWq, uint4* dWq,
             const float4* sWk, uint4* dWk, const float4* sWv, uint4* dWv,
             const float4* sWo, uint4* dWo)
{
    int blk = blockIdx.x;
    const float4* src;
    uint4* dst;
    int base;
    if (blk < 2048)       { src = sXq; dst = dXq; base = blk; }
    else if (blk < 6144)  { src = sXk; dst = dXk; base = blk - 2048; }
    else if (blk < 10240) { src = sXv; dst = dXv; base = blk - 6144; }
    else if (blk < 10752) { src = sWq; dst = dWq; base = blk - 10240; }
    else if (blk < 11264) { src = sWk; dst = dWk; base = blk - 10752; }
    else if (blk < 11776) { src = sWv; dst = dWv; base = blk - 11264; }
    else                  { src = sWo; dst = dWo; base = blk - 11776; }
    int i = base * 256 + threadIdx.x;
    float4 a = src[2 * i], b = src[2 * i + 1];
    uint4 o;
    o.x = packh2(a.x, a.y);
    o.y = packh2(a.z, a.w);
    o.z = packh2(b.x, b.y);
    o.w = packh2(b.z, b.w);
    dst[i] = o;
}

// ---------------------------------------------------------------------------
// fp16 GEMM: out = X @ W^T + bias. CTA 128x128, BK=64, 8 warps (4m x 2n),
// 3-stage cp.async pipeline, ONE barrier per iteration, prefetch-before-compute.
// ---------------------------------------------------------------------------
#define GSTR 72
#define GSTG (128 * GSTR)    // halves per tensor per stage

__global__ __launch_bounds__(256, 2)
void gemm_f16(const __half* __restrict__ A, const __half* __restrict__ W,
              const float* __restrict__ bias, void* __restrict__ outv,
              int nP, int split)
{
    extern __shared__ __half smh[];

    const int tid = threadIdx.x;
    const int wid = tid >> 5;
    const int lane = tid & 31;
    const int g = lane >> 2;
    const int tq = lane & 3;
    const int wm = wid & 3;
    const int wn = wid >> 2;
    const int row0 = blockIdx.y * 128;
    const int col0 = blockIdx.x * 128;

    const uint32_t aoff = (uint32_t)((((lane & 7) + ((lane >> 3) & 1) * 8) * GSTR
                                      + ((lane >> 4) & 1) * 8) * 2);
    const uint32_t boff = (uint32_t)((((lane & 7) + ((lane >> 4) & 1) * 8) * GSTR
                                      + ((lane >> 3) & 1) * 8) * 2);

    float c[2][8][4];
#pragma unroll
    for (int mt = 0; mt < 2; mt++)
#pragma unroll
        for (int nt = 0; nt < 8; nt++)
#pragma unroll
            for (int i = 0; i < 4; i++) c[mt][nt][i] = 0.f;

    auto load_stage = [&](int s, int k0) {
        __half* As = smh + s * 2 * GSTG;
        __half* Bs = As + GSTG;
#pragma unroll
        for (int i = 0; i < 4; i++) {
            int f = tid + i * 256;
            int r = f >> 3, cc = f & 7;
            CP_ASYNC16(smem_u32(&As[r * GSTR + cc * 8]),
                       A + (size_t)(row0 + r) * EMBED + k0 + cc * 8);
            CP_ASYNC16(smem_u32(&Bs[r * GSTR + cc * 8]),
                       W + (size_t)(col0 + r) * EMBED + k0 + cc * 8);
        }
    };

    load_stage(0, 0);  CP_COMMIT();
    load_stage(1, 64); CP_COMMIT();

    for (int it = 0; it < 16; it++) {
        CP_WAIT1();                       // stage it resident
        __syncthreads();                  // all warps done reading slot (it-1)%3
        if (it + 2 < 16) load_stage((it + 2) % 3, (it + 2) * 64);
        CP_COMMIT();                      // commit (possibly empty) to keep counts aligned

        const __half* As = smh + (it % 3) * 2 * GSTG;
        const uint32_t Abase = smem_u32(As) + aoff;
        const uint32_t Bbase = smem_u32(As + GSTG) + boff;

#pragma unroll
        for (int ks = 0; ks < 4; ks++) {
            uint32_t a[2][4];
#pragma unroll
            for (int mt = 0; mt < 2; mt++)
                ldmx4(a[mt][0], a[mt][1], a[mt][2], a[mt][3],
                      Abase + (uint32_t)(((wm * 32 + mt * 16) * GSTR + ks * 16) * 2));
#pragma unroll
            for (int ntp = 0; ntp < 4; ntp++) {
                uint32_t b0, b1, b2, b3;
                ldmx4(b0, b1, b2, b3,
                      Bbase + (uint32_t)(((wn * 64 + ntp * 16) * GSTR + ks * 16) * 2));
                uint32_t blo[2] = {b0, b1};
                uint32_t bhi[2] = {b2, b3};
#pragma unroll
                for (int mt = 0; mt < 2; mt++) {
                    mma_f16(c[mt][2 * ntp], a[mt], blo);
                    mma_f16(c[mt][2 * ntp + 1], a[mt], bhi);
                }
            }
        }
    }

    // epilogue
#pragma unroll
    for (int mt = 0; mt < 2; mt++) {
#pragma unroll
        for (int half_ = 0; half_ < 2; half_++) {
            int grow = row0 + wm * 32 + mt * 16 + g + half_ * 8;
            int bb = grow / nP, n = grow - bb * nP;
#pragma unroll
            for (int nt = 0; nt < 8; nt++) {
                int gcol = col0 + wn * 64 + nt * 8 + tq * 2;
                float v0 = c[mt][nt][half_ * 2 + 0] + bias[gcol];
                float v1 = c[mt][nt][half_ * 2 + 1] + bias[gcol + 1];
                if (split == 1) {
                    int h = gcol >> 6, d = gcol & 63;
                    uint32_t* op = (uint32_t*)((__half*)outv +
                        (((size_t)bb * HEADS + h) * nP + n) * HDIM + d);
                    *op = packh2(v0, v1);
                } else {
                    float2* op = (float2*)((float*)outv + (size_t)grow * EMBED + gcol);
                    *op = make_float2(v0, v1);
                }
            }
        }
    }
}

// ---------------------------------------------------------------------------
// Attention, fp16 mma + ldmatrix, 3-stage cp.async K/V pipeline, one barrier
// per chunk. CTA: 128 q (8 warps x 16q), 64-key chunks.
// ---------------------------------------------------------------------------
#define ASTR 72
#define Q_HALVES (128 * ASTR)
#define KV_HALVES (64 * ASTR)

__global__ __launch_bounds__(256, 2)
void attn5(const __half* __restrict__ Q, const __half* __restrict__ K,
           const __half* __restrict__ V, const float* __restrict__ mult,
           __half* __restrict__ Out)
{
    extern __shared__ __half sh[];
    __half* Qs = sh;

    const int tid  = threadIdx.x;
    const int w    = tid >> 5;
    const int lane = tid & 31;
    const int g    = lane >> 2;
    const int tq   = lane & 3;
    const int bx = blockIdx.x;
    const int q0 = (bx & 7) * 128;
    const int h  = (bx >> 3) & 15;
    const int b  = bx >> 7;

    const __half* Qbase = Q + (((size_t)(b * HEADS + h) * NQ) + q0) * HDIM;
    const __half* Kbase = K + ((size_t)(b * HEADS + h) * NK) * HDIM;
    const __half* Vbase = V + ((size_t)(b * HEADS + h) * NK) * HDIM;
    const float* mbase = mult + (size_t)b * NK;

    // Q tile load joins the first commit group
#pragma unroll
    for (int i = 0; i < 4; i++) {
        int f = tid + i * 256;
        int r = f >> 3, cc = f & 7;
        CP_ASYNC16(smem_u32(&Qs[r * ASTR + cc * 8]),
                   Qbase + (size_t)r * HDIM + cc * 8);
    }

    auto load_kv = [&](int s, int c0) {
        __half* Ks = sh + Q_HALVES + s * 2 * KV_HALVES;
        __half* Vs = Ks + KV_HALVES;
#pragma unroll
        for (int i = 0; i < 2; i++) {
            int f = tid + i * 256;
            int r = f >> 3, cc = f & 7;
            CP_ASYNC16(smem_u32(&Ks[r * ASTR + cc * 8]),
                       Kbase + (size_t)(c0 + r) * HDIM + cc * 8);
            CP_ASYNC16(smem_u32(&Vs[r * ASTR + cc * 8]),
                       Vbase + (size_t)(c0 + r) * HDIM + cc * 8);
        }
    };

    load_kv(0, 0);  CP_COMMIT();   // group: Q + chunk0
    load_kv(1, 64); CP_COMMIT();   // group: chunk1

    const int qb = w * 16;
    const uint32_t aoff = (uint32_t)((((lane & 7) + ((lane >> 3) & 1) * 8) * ASTR
                                      + ((lane >> 4) & 1) * 8) * 2);
    const uint32_t boff = (uint32_t)((((lane & 7) + ((lane >> 4) & 1) * 8) * ASTR
                                      + ((lane >> 3) & 1) * 8) * 2);
    const int mi = lane >> 3, rl = lane & 7;
    const uint32_t vlane_off = (uint32_t)((rl + 8 * (mi & 1)) * ASTR + 8 * (mi >> 1));

    float m0 = -INFINITY, m1 = -INFINITY, l0 = 0.f, l1 = 0.f;
    float Oc[8][4];
#pragma unroll
    for (int dt = 0; dt < 8; dt++)
#pragma unroll
        for (int i = 0; i < 4; i++) Oc[dt][i] = 0.f;

    const uint32_t Qsb = smem_u32(Qs) + aoff + (uint32_t)(qb * ASTR * 2);

    for (int cidx = 0; cidx < 32; cidx++) {
        const int c0 = cidx * 64;
        float2 mv = *(const float2*)(mbase + c0 + 2 * lane);
        float lm0 = __logf(mv.x);
        float lm1 = __logf(mv.y);

        CP_WAIT1();                    // chunk cidx (and Q) resident
        __syncthreads();               // all warps done with slot (cidx-1)%3
        if (cidx + 2 < 32) load_kv((cidx + 2) % 3, c0 + 128);
        CP_COMMIT();

        const __half* Ksh = sh + Q_HALVES + (cidx % 3) * 2 * KV_HALVES;
        const uint32_t Kb = smem_u32(Ksh) + boff;
        const uint32_t vbase = smem_u32(Ksh + KV_HALVES) + vlane_off * 2;

        // ---- S = Q K^T ----
        float Sc[8][4];
#pragma unroll
        for (int nt = 0; nt < 8; nt++)
#pragma unroll
            for (int i = 0; i < 4; i++) Sc[nt][i] = 0.f;

#pragma unroll
        for (int ks = 0; ks < 4; ks++) {
            uint32_t a[4];
            ldmx4(a[0], a[1], a[2], a[3], Qsb + (uint32_t)(ks * 32));
#pragma unroll
            for (int ntp = 0; ntp < 4; ntp++) {
                uint32_t b0, b1, b2, b3;
                ldmx4(b0, b1, b2, b3,
                      Kb + (uint32_t)((ntp * 16 * ASTR + ks * 16) * 2));
                uint32_t blo[2] = {b0, b1};
                uint32_t bhi[2] = {b2, b3};
                mma_f16(Sc[2 * ntp], a, blo);
                mma_f16(Sc[2 * ntp + 1], a, bhi);
            }
        }

        // ---- softmax ----
        float rmax0 = -INFINITY, rmax1 = -INFINITY;
#pragma unroll
        for (int nt = 0; nt < 8; nt++) {
            float lmA = __shfl_sync(0xffffffffu, lm0, nt * 4 + tq);
            float lmB = __shfl_sync(0xffffffffu, lm1, nt * 4 + tq);
            Sc[nt][0] = Sc[nt][0] * 0.125f + lmA;
            Sc[nt][1] = Sc[nt][1] * 0.125f + lmB;
            Sc[nt][2] = Sc[nt][2] * 0.125f + lmA;
            Sc[nt][3] = Sc[nt][3] * 0.125f + lmB;
            rmax0 = fmaxf(rmax0, fmaxf(Sc[nt][0], Sc[nt][1]));
            rmax1 = fmaxf(rmax1, fmaxf(Sc[nt][2], Sc[nt][3]));
        }
        rmax0 = fmaxf(rmax0, __shfl_xor_sync(0xffffffffu, rmax0, 1));
        rmax0 = fmaxf(rmax0, __shfl_xor_sync(0xffffffffu, rmax0, 2));
        rmax1 = fmaxf(rmax1, __shfl_xor_sync(0xffffffffu, rmax1, 1));
        rmax1 = fmaxf(rmax1, __shfl_xor_sync(0xffffffffu, rmax1, 2));

        float mn0 = fmaxf(m0, rmax0);
        float mn1 = fmaxf(m1, rmax1);
        float alpha0 = __expf(m0 - mn0);
        float alpha1 = __expf(m1 - mn1);
        m0 = mn0; m1 = mn1;

        float ls0 = 0.f, ls1 = 0.f;
#pragma unroll
        for (int nt = 0; nt < 8; nt++) {
            Sc[nt][0] = __expf(Sc[nt][0] - mn0);
            Sc[nt][1] = __expf(Sc[nt][1] - mn0);
            Sc[nt][2] = __expf(Sc[nt][2] - mn1);
            Sc[nt][3] = __expf(Sc[nt][3] - mn1);
            ls0 += Sc[nt][0] + Sc[nt][1];
            ls1 += Sc[nt][2] + Sc[nt][3];
        }
        ls0 += __shfl_xor_sync(0xffffffffu, ls0, 1);
        ls0 += __shfl_xor_sync(0xffffffffu, ls0, 2);
        ls1 += __shfl_xor_sync(0xffffffffu, ls1, 1);
        ls1 += __shfl_xor_sync(0xffffffffu, ls1, 2);
        l0 = l0 * alpha0 + ls0;
        l1 = l1 * alpha1 + ls1;

#pragma unroll
        for (int dt = 0; dt < 8; dt++) {
            Oc[dt][0] *= alpha0; Oc[dt][1] *= alpha0;
            Oc[dt][2] *= alpha1; Oc[dt][3] *= alpha1;
        }

        // ---- P C-frags -> fp16 A-frags ----
        uint32_t Pa[4][4];
#pragma unroll
        for (int j = 0; j < 4; j++) {
            Pa[j][0] = packh2(Sc[2 * j][0],     Sc[2 * j][1]);
            Pa[j][1] = packh2(Sc[2 * j][2],     Sc[2 * j][3]);
            Pa[j][2] = packh2(Sc[2 * j + 1][0], Sc[2 * j + 1][1]);
            Pa[j][3] = packh2(Sc[2 * j + 1][2], Sc[2 * j + 1][3]);
        }

        // ---- O += P V ----
#pragma unroll
        for (int j = 0; j < 4; j++) {
            const uint32_t abase = vbase + j * (16 * ASTR * 2);
#pragma unroll
            for (int dtp = 0; dtp < 4; dtp++) {
                uint32_t r0, r1, r2, r3;
                ldmx4_trans(r0, r1, r2, r3, abase + dtp * 32);
                uint32_t blo[2] = {r0, r1};
                uint32_t bhi[2] = {r2, r3};
                mma_f16(Oc[2 * dtp],     Pa[j], blo);
                mma_f16(Oc[2 * dtp + 1], Pa[j], bhi);
            }
        }
    }

    // ---- write out fp16 ----
    const float inv0 = 1.f / l0;
    const float inv1 = 1.f / l1;
    const int qg0 = q0 + qb + g;
    __half* o0 = Out + ((size_t)(b * NQ + qg0)) * EMBED + h * HDIM;
    __half* o1 = o0 + (size_t)8 * EMBED;
#pragma unroll
    for (int dt = 0; dt < 8; dt++) {
        int col = dt * 8 + 2 * tq;
        *(uint32_t*)(o0 + col) = packh2(Oc[dt][0] * inv0, Oc[dt][1] * inv0);
        *(uint32_t*)(o1 + col) = packh2(Oc[dt][2] * inv1, Oc[dt][3] * inv1);
    }
}

// ---------------------------------------------------------------------------
// launch
// ---------------------------------------------------------------------------
extern "C" void kernel_launch(void* const* d_in, const int* in_sizes, int n_in,
                              void* d_out, int out_size)
{
    const float* query = (const float*)d_in[0];
    const float* key   = (const float*)d_in[1];
    const float* value = (const float*)d_in[2];
    const float* mult  = (const float*)d_in[3];
    const float* wq_w  = (const float*)d_in[4];
    const float* wq_b  = (const float*)d_in[5];
    const float* wk_w  = (const float*)d_in[6];
    const float* wk_b  = (const float*)d_in[7];
    const float* wv_w  = (const float*)d_in[8];
    const float* wv_b  = (const float*)d_in[9];
    const float* wo_w  = (const float*)d_in[10];
    const float* wo_b  = (const float*)d_in[11];
    float* out = (float*)d_out;

    __half *gQ, *gK, *gV, *gA, *gXq, *gXk, *gXv, *gWq, *gWk, *gWv, *gWo;
    cudaGetSymbolAddress((void**)&gQ, g_Q);
    cudaGetSymbolAddress((void**)&gK, g_K);
    cudaGetSymbolAddress((void**)&gV, g_V);
    cudaGetSymbolAddress((void**)&gA, g_A);
    cudaGetSymbolAddress((void**)&gXq, g_Xq);
    cudaGetSymbolAddress((void**)&gXk, g_Xk);
    cudaGetSymbolAddress((void**)&gXv, g_Xv);
    cudaGetSymbolAddress((void**)&gWq, g_Wq);
    cudaGetSymbolAddress((void**)&gWk, g_Wk);
    cudaGetSymbolAddress((void**)&gWv, g_Wv);
    cudaGetSymbolAddress((void**)&gWo, g_Wo);

    const int GEMM_SMEM = 3 * 2 * GSTG * 2;                    // 110592
    const int ATTN_SMEM = (Q_HALVES + 3 * 2 * KV_HALVES) * 2;  // 73728
    cudaFuncSetAttribute(gemm_f16, cudaFuncAttributeMaxDynamicSharedMemorySize, GEMM_SMEM);
    cudaFuncSetAttribute(attn5, cudaFuncAttributeMaxDynamicSharedMemorySize, ATTN_SMEM);

    dim3 blk(256);
    cvt_all<<<12288, blk>>>((const float4*)query, (uint4*)gXq,
                            (const float4*)key,   (uint4*)gXk,
                            (const float4*)value, (uint4*)gXv,
                            (const float4*)wq_w,  (uint4*)gWq,
                            (const float4*)wk_w,  (uint4*)gWk,
                            (const float4*)wv_w,  (uint4*)gWv,
                            (const float4*)wo_w,  (uint4*)gWo);

    gemm_f16<<<dim3(8, 32), blk, GEMM_SMEM>>>(gXq, gWq, wq_b, gQ, NQ, 1);
    gemm_f16<<<dim3(8, 64), blk, GEMM_SMEM>>>(gXk, gWk, wk_b, gK, NK, 1);
    gemm_f16<<<dim3(8, 64), blk, GEMM_SMEM>>>(gXv, gWv, wv_b, gV, NK, 1);

    attn5<<<BATCH * HEADS * (NQ / 128), blk, ATTN_SMEM>>>(gQ, gK, gV, mult, gA);

    gemm_f16<<<dim3(8, 32), blk, GEMM_SMEM>>>(gA, gWo, wo_b, out, NQ, 0);
}

// round 14
// speedup vs baseline: 21.1315x; 1.0686x over previous
#include <cuda_runtime.h>
#include <cuda_fp16.h>
#include <cstdint>
#include <math.h>

#define EMBED 1024
#define HEADS 16
#define HDIM  64
#define BATCH 4
#define NQ    1024
#define NK    2048

// Scratch (static device memory) — fp16 operands
__device__ __half g_Q[(size_t)BATCH * HEADS * NQ * HDIM];
__device__ __half g_K[(size_t)BATCH * HEADS * NK * HDIM];
__device__ __half g_V[(size_t)BATCH * HEADS * NK * HDIM];
__device__ __half g_A[(size_t)BATCH * NQ * EMBED];
__device__ __half g_Xq[(size_t)BATCH * NQ * EMBED];
__device__ __half g_Xk[(size_t)BATCH * NK * EMBED];
__device__ __half g_Xv[(size_t)BATCH * NK * EMBED];
__device__ __half g_Wq[(size_t)EMBED * EMBED];
__device__ __half g_Wk[(size_t)EMBED * EMBED];
__device__ __half g_Wv[(size_t)EMBED * EMBED];
__device__ __half g_Wo[(size_t)EMBED * EMBED];

__device__ __forceinline__ uint32_t smem_u32(const void* p) {
    return (uint32_t)__cvta_generic_to_shared(p);
}
__device__ __forceinline__ uint32_t packh2(float a, float b) {
    __half2 h = __floats2half2_rn(a, b);
    return *(uint32_t*)&h;
}

#define CP_ASYNC16(dst_u32, src_ptr) \
    asm volatile("cp.async.cg.shared.global [%0], [%1], 16;" :: "r"(dst_u32), "l"(src_ptr))
#define CP_COMMIT() asm volatile("cp.async.commit_group;")
#define CP_WAIT1()  asm volatile("cp.async.wait_group 1;")

__device__ __forceinline__ void mma_f16(float* c, const uint32_t* a, const uint32_t* b) {
    asm volatile(
        "mma.sync.aligned.m16n8k16.row.col.f32.f16.f16.f32 "
        "{%0,%1,%2,%3}, {%4,%5,%6,%7}, {%8,%9}, {%0,%1,%2,%3};"
        : "+f"(c[0]), "+f"(c[1]), "+f"(c[2]), "+f"(c[3])
        : "r"(a[0]), "r"(a[1]), "r"(a[2]), "r"(a[3]), "r"(b[0]), "r"(b[1]));
}
__device__ __forceinline__ void ldmx4(uint32_t& r0, uint32_t& r1, uint32_t& r2, uint32_t& r3,
                                      uint32_t addr) {
    asm volatile("ldmatrix.sync.aligned.m8n8.x4.shared.b16 {%0,%1,%2,%3}, [%4];"
                 : "=r"(r0), "=r"(r1), "=r"(r2), "=r"(r3) : "r"(addr));
}
__device__ __forceinline__ void ldmx4_trans(uint32_t& r0, uint32_t& r1, uint32_t& r2, uint32_t& r3,
                                            uint32_t addr) {
    asm volatile("ldmatrix.sync.aligned.m8n8.x4.trans.shared.b16 {%0,%1,%2,%3}, [%4];"
                 : "=r"(r0), "=r"(r1), "=r"(r2), "=r"(r3) : "r"(addr));
}

// ---------------------------------------------------------------------------
// Fused prepass: fp32 -> fp16 for all 7 tensors in one launch.
// ---------------------------------------------------------------------------
__global__ __launch_bounds__(256)
void cvt_all(const float4* sXq, uint4* dXq, const float4* sXk, uint4* dXk,
             const float4* sXv, uint4* dXv, const float4* sWq, uint4* dWq,
             const float4* sWk, uint4* dWk, const float4* sWv, uint4* dWv,
             const float4* sWo, uint4* dWo)
{
    int blk = blockIdx.x;
    const float4* src;
    uint4* dst;
    int base;
    if (blk < 2048)       { src = sXq; dst = dXq; base = blk; }
    else if (blk < 6144)  { src = sXk; dst = dXk; base = blk - 2048; }
    else if (blk < 10240) { src = sXv; dst = dXv; base = blk - 6144; }
    else if (blk < 10752) { src = sWq; dst = dWq; base = blk - 10240; }
    else if (blk < 11264) { src = sWk; dst = dWk; base = blk - 10752; }
    else if (blk < 11776) { src = sWv; dst = dWv; base = blk - 11264; }
    else                  { src = sWo; dst = dWo; base = blk - 11776; }
    int i = base * 256 + threadIdx.x;
    float4 a = src[2 * i], b = src[2 * i + 1];
    uint4 o;
    o.x = packh2(a.x, a.y);
    o.y = packh2(a.z, a.w);
    o.z = packh2(b.x, b.y);
    o.w = packh2(b.z, b.w);
    dst[i] = o;
}

// ---------------------------------------------------------------------------
// Shared GEMM body pieces
// ---------------------------------------------------------------------------
#define GSTR 72
#define GSTG (128 * GSTR)    // halves per tensor per stage

// Mainloop macro body implemented as a device function (keeps both kernels small)
struct GemmCtx {
    const __half* A;
    const __half* W;
    int row0, col0;
};

__device__ __forceinline__ void gemm_mainloop(
    __half* smh, const __half* __restrict__ A, const __half* __restrict__ W,
    int row0, int col0, int tid, int wm, int wn,
    uint32_t aoff, uint32_t boff, float c[2][8][4])
{
    auto load_stage = [&](int s, int k0) {
        __half* As = smh + s * 2 * GSTG;
        __half* Bs = As + GSTG;
#pragma unroll
        for (int i = 0; i < 4; i++) {
            int f = tid + i * 256;
            int r = f >> 3, cc = f & 7;
            CP_ASYNC16(smem_u32(&As[r * GSTR + cc * 8]),
                       A + (size_t)(row0 + r) * EMBED + k0 + cc * 8);
            CP_ASYNC16(smem_u32(&Bs[r * GSTR + cc * 8]),
                       W + (size_t)(col0 + r) * EMBED + k0 + cc * 8);
        }
    };

    load_stage(0, 0);  CP_COMMIT();
    load_stage(1, 64); CP_COMMIT();

    for (int it = 0; it < 16; it++) {
        CP_WAIT1();
        __syncthreads();
        if (it + 2 < 16) load_stage((it + 2) % 3, (it + 2) * 64);
        CP_COMMIT();

        const __half* As = smh + (it % 3) * 2 * GSTG;
        const uint32_t Abase = smem_u32(As) + aoff;
        const uint32_t Bbase = smem_u32(As + GSTG) + boff;

        // register double-buffered fragments
        uint32_t af[2][2][4], bf[2][4][4];
#pragma unroll
        for (int mt = 0; mt < 2; mt++)
            ldmx4(af[0][mt][0], af[0][mt][1], af[0][mt][2], af[0][mt][3],
                  Abase + (uint32_t)(((wm * 32 + mt * 16) * GSTR) * 2));
#pragma unroll
        for (int ntp = 0; ntp < 4; ntp++)
            ldmx4(bf[0][ntp][0], bf[0][ntp][1], bf[0][ntp][2], bf[0][ntp][3],
                  Bbase + (uint32_t)(((wn * 64 + ntp * 16) * GSTR) * 2));

#pragma unroll
        for (int ks = 0; ks < 4; ks++) {
            const int cb = ks & 1;
            const int nb = cb ^ 1;
            if (ks < 3) {
#pragma unroll
                for (int mt = 0; mt < 2; mt++)
                    ldmx4(af[nb][mt][0], af[nb][mt][1], af[nb][mt][2], af[nb][mt][3],
                          Abase + (uint32_t)(((wm * 32 + mt * 16) * GSTR + (ks + 1) * 16) * 2));
#pragma unroll
                for (int ntp = 0; ntp < 4; ntp++)
                    ldmx4(bf[nb][ntp][0], bf[nb][ntp][1], bf[nb][ntp][2], bf[nb][ntp][3],
                          Bbase + (uint32_t)(((wn * 64 + ntp * 16) * GSTR + (ks + 1) * 16) * 2));
            }
#pragma unroll
            for (int ntp = 0; ntp < 4; ntp++) {
#pragma unroll
                for (int mt = 0; mt < 2; mt++) {
                    mma_f16(c[mt][2 * ntp],     af[cb][mt], &bf[cb][ntp][0]);
                    mma_f16(c[mt][2 * ntp + 1], af[cb][mt], &bf[cb][ntp][2]);
                }
            }
        }
    }
}

// ---------------------------------------------------------------------------
// Merged Q/K/V projection GEMM: one launch, grid (8, 160).
// by<32: Q (nP=NQ); by<96: K; else V. All write fp16 head-split (b,h,n,d).
// ---------------------------------------------------------------------------
__global__ __launch_bounds__(256, 2)
void gemm_qkv(const __half* __restrict__ Xq, const __half* __restrict__ Wq,
              const float* __restrict__ bq, __half* __restrict__ Oq,
              const __half* __restrict__ Xk, const __half* __restrict__ Wk,
              const float* __restrict__ bk, __half* __restrict__ Ok,
              const __half* __restrict__ Xv, const __half* __restrict__ Wv,
              const float* __restrict__ bv, __half* __restrict__ Ov)
{
    extern __shared__ __half smh[];

    const int by = blockIdx.y;
    const __half *A, *W;
    const float* bias;
    __half* out;
    int nP, rb;
    if (by < 32)      { A = Xq; W = Wq; bias = bq; out = Oq; nP = NQ; rb = by; }
    else if (by < 96) { A = Xk; W = Wk; bias = bk; out = Ok; nP = NK; rb = by - 32; }
    else              { A = Xv; W = Wv; bias = bv; out = Ov; nP = NK; rb = by - 96; }

    const int tid = threadIdx.x;
    const int wid = tid >> 5;
    const int lane = tid & 31;
    const int g = lane >> 2;
    const int tq = lane & 3;
    const int wm = wid & 3;
    const int wn = wid >> 2;
    const int row0 = rb * 128;
    const int col0 = blockIdx.x * 128;

    const uint32_t aoff = (uint32_t)((((lane & 7) + ((lane >> 3) & 1) * 8) * GSTR
                                      + ((lane >> 4) & 1) * 8) * 2);
    const uint32_t boff = (uint32_t)((((lane & 7) + ((lane >> 4) & 1) * 8) * GSTR
                                      + ((lane >> 3) & 1) * 8) * 2);

    float c[2][8][4];
#pragma unroll
    for (int mt = 0; mt < 2; mt++)
#pragma unroll
        for (int nt = 0; nt < 8; nt++)
#pragma unroll
            for (int i = 0; i < 4; i++) c[mt][nt][i] = 0.f;

    gemm_mainloop(smh, A, W, row0, col0, tid, wm, wn, aoff, boff, c);

    // epilogue: fp16 head-split
#pragma unroll
    for (int mt = 0; mt < 2; mt++) {
#pragma unroll
        for (int half_ = 0; half_ < 2; half_++) {
            int grow = row0 + wm * 32 + mt * 16 + g + half_ * 8;
            int bb = grow / nP, n = grow - bb * nP;
#pragma unroll
            for (int nt = 0; nt < 8; nt++) {
                int gcol = col0 + wn * 64 + nt * 8 + tq * 2;
                float v0 = c[mt][nt][half_ * 2 + 0] + bias[gcol];
                float v1 = c[mt][nt][half_ * 2 + 1] + bias[gcol + 1];
                int h = gcol >> 6, d = gcol & 63;
                uint32_t* op = (uint32_t*)(out +
                    (((size_t)bb * HEADS + h) * nP + n) * HDIM + d);
                *op = packh2(v0, v1);
            }
        }
    }
}

// ---------------------------------------------------------------------------
// Output projection GEMM: fp32 plain output.
// ---------------------------------------------------------------------------
__global__ __launch_bounds__(256, 2)
void gemm_o(const __half* __restrict__ A, const __half* __restrict__ W,
            const float* __restrict__ bias, float* __restrict__ out)
{
    extern __shared__ __half smh[];

    const int tid = threadIdx.x;
    const int wid = tid >> 5;
    const int lane = tid & 31;
    const int g = lane >> 2;
    const int tq = lane & 3;
    const int wm = wid & 3;
    const int wn = wid >> 2;
    const int row0 = blockIdx.y * 128;
    const int col0 = blockIdx.x * 128;

    const uint32_t aoff = (uint32_t)((((lane & 7) + ((lane >> 3) & 1) * 8) * GSTR
                                      + ((lane >> 4) & 1) * 8) * 2);
    const uint32_t boff = (uint32_t)((((lane & 7) + ((lane >> 4) & 1) * 8) * GSTR
                                      + ((lane >> 3) & 1) * 8) * 2);

    float c[2][8][4];
#pragma unroll
    for (int mt = 0; mt < 2; mt++)
#pragma unroll
        for (int nt = 0; nt < 8; nt++)
#pragma unroll
            for (int i = 0; i < 4; i++) c[mt][nt][i] = 0.f;

    gemm_mainloop(smh, A, W, row0, col0, tid, wm, wn, aoff, boff, c);

#pragma unroll
    for (int mt = 0; mt < 2; mt++) {
#pragma unroll
        for (int half_ = 0; half_ < 2; half_++) {
            int grow = row0 + wm * 32 + mt * 16 + g + half_ * 8;
#pragma unroll
            for (int nt = 0; nt < 8; nt++) {
                int gcol = col0 + wn * 64 + nt * 8 + tq * 2;
                float v0 = c[mt][nt][half_ * 2 + 0] + bias[gcol];
                float v1 = c[mt][nt][half_ * 2 + 1] + bias[gcol + 1];
                *(float2*)(out + (size_t)grow * EMBED + gcol) = make_float2(v0, v1);
            }
        }
    }
}

// ---------------------------------------------------------------------------
// Attention, fp16 mma + ldmatrix, 3-stage cp.async K/V pipeline.
// CTA: 128 q (8 warps x 16q), 64-key chunks.
// ---------------------------------------------------------------------------
#define ASTR 72
#define Q_HALVES (128 * ASTR)
#define KV_HALVES (64 * ASTR)

__global__ __launch_bounds__(256, 2)
void attn5(const __half* __restrict__ Q, const __half* __restrict__ K,
           const __half* __restrict__ V, const float* __restrict__ mult,
           __half* __restrict__ Out)
{
    extern __shared__ __half sh[];
    __half* Qs = sh;

    const int tid  = threadIdx.x;
    const int w    = tid >> 5;
    const int lane = tid & 31;
    const int g    = lane >> 2;
    const int tq   = lane & 3;
    const int bx = blockIdx.x;
    const int q0 = (bx & 7) * 128;
    const int h  = (bx >> 3) & 15;
    const int b  = bx >> 7;

    const __half* Qbase = Q + (((size_t)(b * HEADS + h) * NQ) + q0) * HDIM;
    const __half* Kbase = K + ((size_t)(b * HEADS + h) * NK) * HDIM;
    const __half* Vbase = V + ((size_t)(b * HEADS + h) * NK) * HDIM;
    const float* mbase = mult + (size_t)b * NK;

#pragma unroll
    for (int i = 0; i < 4; i++) {
        int f = tid + i * 256;
        int r = f >> 3, cc = f & 7;
        CP_ASYNC16(smem_u32(&Qs[r * ASTR + cc * 8]),
                   Qbase + (size_t)r * HDIM + cc * 8);
    }

    auto load_kv = [&](int s, int c0) {
        __half* Ks = sh + Q_HALVES + s * 2 * KV_HALVES;
        __half* Vs = Ks + KV_HALVES;
#pragma unroll
        for (int i = 0; i < 2; i++) {
            int f = tid + i * 256;
            int r = f >> 3, cc = f & 7;
            CP_ASYNC16(smem_u32(&Ks[r * ASTR + cc * 8]),
                       Kbase + (size_t)(c0 + r) * HDIM + cc * 8);
            CP_ASYNC16(smem_u32(&Vs[r * ASTR + cc * 8]),
                       Vbase + (size_t)(c0 + r) * HDIM + cc * 8);
        }
    };

    load_kv(0, 0);  CP_COMMIT();
    load_kv(1, 64); CP_COMMIT();

    const int qb = w * 16;
    const uint32_t aoff = (uint32_t)((((lane & 7) + ((lane >> 3) & 1) * 8) * ASTR
                                      + ((lane >> 4) & 1) * 8) * 2);
    const uint32_t boff = (uint32_t)((((lane & 7) + ((lane >> 4) & 1) * 8) * ASTR
                                      + ((lane >> 3) & 1) * 8) * 2);
    const int mi = lane >> 3, rl = lane & 7;
    const uint32_t vlane_off = (uint32_t)((rl + 8 * (mi & 1)) * ASTR + 8 * (mi >> 1));

    float m0 = -INFINITY, m1 = -INFINITY, l0 = 0.f, l1 = 0.f;
    float Oc[8][4];
#pragma unroll
    for (int dt = 0; dt < 8; dt++)
#pragma unroll
        for (int i = 0; i < 4; i++) Oc[dt][i] = 0.f;

    const uint32_t Qsb = smem_u32(Qs) + aoff + (uint32_t)(qb * ASTR * 2);

    for (int cidx = 0; cidx < 32; cidx++) {
        const int c0 = cidx * 64;
        float2 mv = *(const float2*)(mbase + c0 + 2 * lane);
        float lm0 = __logf(mv.x);
        float lm1 = __logf(mv.y);

        CP_WAIT1();
        __syncthreads();
        if (cidx + 2 < 32) load_kv((cidx + 2) % 3, c0 + 128);
        CP_COMMIT();

        const __half* Ksh = sh + Q_HALVES + (cidx % 3) * 2 * KV_HALVES;
        const uint32_t Kb = smem_u32(Ksh) + boff;
        const uint32_t vbase = smem_u32(Ksh + KV_HALVES) + vlane_off * 2;

        // ---- S = Q K^T ----
        float Sc[8][4];
#pragma unroll
        for (int nt = 0; nt < 8; nt++)
#pragma unroll
            for (int i = 0; i < 4; i++) Sc[nt][i] = 0.f;

#pragma unroll
        for (int ks = 0; ks < 4; ks++) {
            uint32_t a[4];
            ldmx4(a[0], a[1], a[2], a[3], Qsb + (uint32_t)(ks * 32));
#pragma unroll
            for (int ntp = 0; ntp < 4; ntp++) {
                uint32_t b0, b1, b2, b3;
                ldmx4(b0, b1, b2, b3,
                      Kb + (uint32_t)((ntp * 16 * ASTR + ks * 16) * 2));
                uint32_t blo[2] = {b0, b1};
                uint32_t bhi[2] = {b2, b3};
                mma_f16(Sc[2 * ntp], a, blo);
                mma_f16(Sc[2 * ntp + 1], a, bhi);
            }
        }

        // ---- softmax ----
        float rmax0 = -INFINITY, rmax1 = -INFINITY;
#pragma unroll
        for (int nt = 0; nt < 8; nt++) {
            float lmA = __shfl_sync(0xffffffffu, lm0, nt * 4 + tq);
            float lmB = __shfl_sync(0xffffffffu, lm1, nt * 4 + tq);
            Sc[nt][0] = Sc[nt][0] * 0.125f + lmA;
            Sc[nt][1] = Sc[nt][1] * 0.125f + lmB;
            Sc[nt][2] = Sc[nt][2] * 0.125f + lmA;
            Sc[nt][3] = Sc[nt][3] * 0.125f + lmB;
            rmax0 = fmaxf(rmax0, fmaxf(Sc[nt][0], Sc[nt][1]));
            rmax1 = fmaxf(rmax1, fmaxf(Sc[nt][2], Sc[nt][3]));
        }
        rmax0 = fmaxf(rmax0, __shfl_xor_sync(0xffffffffu, rmax0, 1));
        rmax0 = fmaxf(rmax0, __shfl_xor_sync(0xffffffffu, rmax0, 2));
        rmax1 = fmaxf(rmax1, __shfl_xor_sync(0xffffffffu, rmax1, 1));
        rmax1 = fmaxf(rmax1, __shfl_xor_sync(0xffffffffu, rmax1, 2));

        float mn0 = fmaxf(m0, rmax0);
        float mn1 = fmaxf(m1, rmax1);
        float alpha0 = __expf(m0 - mn0);
        float alpha1 = __expf(m1 - mn1);
        m0 = mn0; m1 = mn1;

        float ls0 = 0.f, ls1 = 0.f;
#pragma unroll
        for (int nt = 0; nt < 8; nt++) {
            Sc[nt][0] = __expf(Sc[nt][0] - mn0);
            Sc[nt][1] = __expf(Sc[nt][1] - mn0);
            Sc[nt][2] = __expf(Sc[nt][2] - mn1);
            Sc[nt][3] = __expf(Sc[nt][3] - mn1);
            ls0 += Sc[nt][0] + Sc[nt][1];
            ls1 += Sc[nt][2] + Sc[nt][3];
        }
        ls0 += __shfl_xor_sync(0xffffffffu, ls0, 1);
        ls0 += __shfl_xor_sync(0xffffffffu, ls0, 2);
        ls1 += __shfl_xor_sync(0xffffffffu, ls1, 1);
        ls1 += __shfl_xor_sync(0xffffffffu, ls1, 2);
        l0 = l0 * alpha0 + ls0;
        l1 = l1 * alpha1 + ls1;

#pragma unroll
        for (int dt = 0; dt < 8; dt++) {
            Oc[dt][0] *= alpha0; Oc[dt][1] *= alpha0;
            Oc[dt][2] *= alpha1; Oc[dt][3] *= alpha1;
        }

        // ---- P C-frags -> fp16 A-frags ----
        uint32_t Pa[4][4];
#pragma unroll
        for (int j = 0; j < 4; j++) {
            Pa[j][0] = packh2(Sc[2 * j][0],     Sc[2 * j][1]);
            Pa[j][1] = packh2(Sc[2 * j][2],     Sc[2 * j][3]);
            Pa[j][2] = packh2(Sc[2 * j + 1][0], Sc[2 * j + 1][1]);
            Pa[j][3] = packh2(Sc[2 * j + 1][2], Sc[2 * j + 1][3]);
        }

        // ---- O += P V ----
#pragma unroll
        for (int j = 0; j < 4; j++) {
            const uint32_t abase = vbase + j * (16 * ASTR * 2);
#pragma unroll
            for (int dtp = 0; dtp < 4; dtp++) {
                uint32_t r0, r1, r2, r3;
                ldmx4_trans(r0, r1, r2, r3, abase + dtp * 32);
                uint32_t blo[2] = {r0, r1};
                uint32_t bhi[2] = {r2, r3};
                mma_f16(Oc[2 * dtp],     Pa[j], blo);
                mma_f16(Oc[2 * dtp + 1], Pa[j], bhi);
            }
        }
    }

    // ---- write out fp16 ----
    const float inv0 = 1.f / l0;
    const float inv1 = 1.f / l1;
    const int qg0 = q0 + qb + g;
    __half* o0 = Out + ((size_t)(b * NQ + qg0)) * EMBED + h * HDIM;
    __half* o1 = o0 + (size_t)8 * EMBED;
#pragma unroll
    for (int dt = 0; dt < 8; dt++) {
        int col = dt * 8 + 2 * tq;
        *(uint32_t*)(o0 + col) = packh2(Oc[dt][0] * inv0, Oc[dt][1] * inv0);
        *(uint32_t*)(o1 + col) = packh2(Oc[dt][2] * inv1, Oc[dt][3] * inv1);
    }
}

// ---------------------------------------------------------------------------
// launch
// ---------------------------------------------------------------------------
extern "C" void kernel_launch(void* const* d_in, const int* in_sizes, int n_in,
                              void* d_out, int out_size)
{
    const float* query = (const float*)d_in[0];
    const float* key   = (const float*)d_in[1];
    const float* value = (const float*)d_in[2];
    const float* mult  = (const float*)d_in[3];
    const float* wq_w  = (const float*)d_in[4];
    const float* wq_b  = (const float*)d_in[5];
    const float* wk_w  = (const float*)d_in[6];
    const float* wk_b  = (const float*)d_in[7];
    const float* wv_w  = (const float*)d_in[8];
    const float* wv_b  = (const float*)d_in[9];
    const float* wo_w  = (const float*)d_in[10];
    const float* wo_b  = (const float*)d_in[11];
    float* out = (float*)d_out;

    __half *gQ, *gK, *gV, *gA, *gXq, *gXk, *gXv, *gWq, *gWk, *gWv, *gWo;
    cudaGetSymbolAddress((void**)&gQ, g_Q);
    cudaGetSymbolAddress((void**)&gK, g_K);
    cudaGetSymbolAddress((void**)&gV, g_V);
    cudaGetSymbolAddress((void**)&gA, g_A);
    cudaGetSymbolAddress((void**)&gXq, g_Xq);
    cudaGetSymbolAddress((void**)&gXk, g_Xk);
    cudaGetSymbolAddress((void**)&gXv, g_Xv);
    cudaGetSymbolAddress((void**)&gWq, g_Wq);
    cudaGetSymbolAddress((void**)&gWk, g_Wk);
    cudaGetSymbolAddress((void**)&gWv, g_Wv);
    cudaGetSymbolAddress((void**)&gWo, g_Wo);

    const int GEMM_SMEM = 3 * 2 * GSTG * 2;                    // 110592
    const int ATTN_SMEM = (Q_HALVES + 3 * 2 * KV_HALVES) * 2;  // 73728
    cudaFuncSetAttribute(gemm_qkv, cudaFuncAttributeMaxDynamicSharedMemorySize, GEMM_SMEM);
    cudaFuncSetAttribute(gemm_o,   cudaFuncAttributeMaxDynamicSharedMemorySize, GEMM_SMEM);
    cudaFuncSetAttribute(attn5, cudaFuncAttributeMaxDynamicSharedMemorySize, ATTN_SMEM);

    dim3 blk(256);
    cvt_all<<<12288, blk>>>((const float4*)query, (uint4*)gXq,
                            (const float4*)key,   (uint4*)gXk,
                            (const float4*)value, (uint4*)gXv,
                            (const float4*)wq_w,  (uint4*)gWq,
                            (const float4*)wk_w,  (uint4*)gWk,
                            (const float4*)wv_w,  (uint4*)gWv,
                            (const float4*)wo_w,  (uint4*)gWo);

    // merged Q/K/V projections (one launch, 1280 CTAs)
    gemm_qkv<<<dim3(8, 160), blk, GEMM_SMEM>>>(gXq, gWq, wq_b, gQ,
                                               gXk, gWk, wk_b, gK,
                                               gXv, gWv, wv_b, gV);

    // attention
    attn5<<<BATCH * HEADS * (NQ / 128), blk, ATTN_SMEM>>>(gQ, gK, gV, mult, gA);

    // output projection
    gemm_o<<<dim3(8, 32), blk, GEMM_SMEM>>>(gA, gWo, wo_b, out);
}